// round 12
// baseline (speedup 1.0000x reference)
#include <cuda_runtime.h>
#include <math.h>

namespace {
constexpr int Bb    = 2;
constexpr int DIN   = 1024;
constexpr int D     = 512;
constexpr int HD    = 64;
constexpr int M_LM  = 256;
constexpr int NPAD  = 16384;
constexpr int NTOK  = 16130;
constexpr int PAD0  = 254;
constexpr int BH    = 16;      // Bb * 8 heads
constexpr int QKV3  = 1536;
constexpr int HW    = 127;
constexpr int NFEAT = HW * HW; // 16129
constexpr float LNEPS = 1e-5f;
}

__device__ float g_h   [(size_t)Bb * NTOK * D];
__device__ float g_h2  [(size_t)Bb * NTOK * D];
__device__ float g_xpad[(size_t)Bb * NPAD * D];
__device__ float g_qkv [(size_t)Bb * NPAD * QKV3];
__device__ float g_ql  [(size_t)BH * M_LM * HD];
__device__ float g_kl  [(size_t)BH * M_LM * HD];
__device__ float g_a2  [(size_t)BH * M_LM * M_LM];
__device__ float g_z0  [(size_t)BH * M_LM * M_LM];
__device__ float g_z1  [(size_t)BH * M_LM * M_LM];
__device__ float g_az  [(size_t)BH * M_LM * M_LM];
__device__ float g_t2  [(size_t)BH * M_LM * M_LM];
__device__ float g_t4  [(size_t)BH * M_LM * M_LM];
__device__ float g_s3  [(size_t)BH * M_LM * NPAD];
__device__ float g_a1  [(size_t)BH * NPAD * M_LM];
__device__ float g_avp [(size_t)BH * 8 * M_LM * HD];
__device__ float g_av  [(size_t)BH * M_LM * HD];
__device__ float g_mid [(size_t)BH * M_LM * HD];
__device__ float g_attnout[(size_t)Bb * NPAD * D];
__device__ float g_clsrow[Bb * D];
__device__ int   g_rmax;
__device__ int   g_cmax;

// ---------------- dense SGEMM: C = A(MxK) * W(NxK)^T (+bias) ----------------
// epi: 0 store, 1 relu-store, 2 accumulate (C += acc+bias)
__global__ void __launch_bounds__(256) k_sgemm(
    const float* __restrict__ A, const float* __restrict__ W,
    const float* __restrict__ bias, float* __restrict__ C,
    int M, int N, int K, long strideA, long strideC, int epi)
{
    const float* Ab = A + (size_t)blockIdx.z * strideA;
    float*       Cb = C + (size_t)blockIdx.z * strideC;
    int bm = blockIdx.y * 128, bn = blockIdx.x * 128;
    __shared__ float As[8][132];
    __shared__ float Ws[8][132];
    int tid = threadIdx.x;
    int lr = tid >> 1, lc = (tid & 1) * 4;
    int ty = tid >> 4, tx = tid & 15;
    float acc[8][8];
#pragma unroll
    for (int i = 0; i < 8; i++)
#pragma unroll
        for (int j = 0; j < 8; j++) acc[i][j] = 0.f;

    for (int k0 = 0; k0 < K; k0 += 8) {
        float4 av = make_float4(0.f,0.f,0.f,0.f);
        if (bm + lr < M)
            av = *(const float4*)&Ab[(size_t)(bm + lr) * K + k0 + lc];
        float4 wv = *(const float4*)&W[(size_t)(bn + lr) * K + k0 + lc];
        As[lc+0][lr]=av.x; As[lc+1][lr]=av.y; As[lc+2][lr]=av.z; As[lc+3][lr]=av.w;
        Ws[lc+0][lr]=wv.x; Ws[lc+1][lr]=wv.y; Ws[lc+2][lr]=wv.z; Ws[lc+3][lr]=wv.w;
        __syncthreads();
#pragma unroll
        for (int k = 0; k < 8; k++) {
            float a[8], b[8];
#pragma unroll
            for (int i = 0; i < 8; i++) a[i] = As[k][ty*8+i];
#pragma unroll
            for (int j = 0; j < 8; j++) b[j] = Ws[k][tx*8+j];
#pragma unroll
            for (int i = 0; i < 8; i++)
#pragma unroll
                for (int j = 0; j < 8; j++)
                    acc[i][j] = fmaf(a[i], b[j], acc[i][j]);
        }
        __syncthreads();
    }
#pragma unroll
    for (int i = 0; i < 8; i++) {
        int row = bm + ty*8 + i;
        if (row >= M) continue;
#pragma unroll
        for (int j = 0; j < 8; j++) {
            int col = bn + tx*8 + j;
            float v = acc[i][j] + bias[col];
            size_t idx = (size_t)row * N + col;
            if (epi == 1) v = fmaxf(v, 0.f);
            if (epi == 2) Cb[idx] += v; else Cb[idx] = v;
        }
    }
}

// cls token into row 0, wrap rows 16001..16129 from rows 1..129
__global__ void k_fixup(const float* __restrict__ cls)
{
    int b = blockIdx.y, r = blockIdx.x, c = threadIdx.x; // 512 thr
    if (r == 0) g_h[(size_t)b * NTOK * D + c] = cls[c];
    else {
        int j = r - 1;
        g_h[((size_t)b*NTOK + 16001 + j)*D + c] = g_h[((size_t)b*NTOK + 1 + j)*D + c];
    }
}

__global__ void k_lnpad(const float* __restrict__ hin,
                        const float* __restrict__ w, const float* __restrict__ b)
{
    int row = blockIdx.x, bb = blockIdx.y, t = threadIdx.x; // 256 thr
    float* out = g_xpad + ((size_t)bb * NPAD + row) * D;
    if (row < PAD0) { out[t] = 0.f; out[t+256] = 0.f; return; }
    const float* in = hin + ((size_t)bb * NTOK + row - PAD0) * D;
    float x0 = in[t], x1 = in[t+256];
    __shared__ float red[256];
    red[t] = x0 + x1; __syncthreads();
    for (int s = 128; s > 0; s >>= 1) { if (t < s) red[t] += red[t+s]; __syncthreads(); }
    float mu = red[0] * (1.f/512.f); __syncthreads();
    float d0 = x0 - mu, d1 = x1 - mu;
    red[t] = d0*d0 + d1*d1; __syncthreads();
    for (int s = 128; s > 0; s >>= 1) { if (t < s) red[t] += red[t+s]; __syncthreads(); }
    float rs = rsqrtf(red[0] * (1.f/512.f) + LNEPS);
    out[t]     = d0 * rs * w[t]     + b[t];
    out[t+256] = d1 * rs * w[t+256] + b[t+256];
}

__global__ void k_landmarks()
{
    int bh = blockIdx.y, j = blockIdx.x, dd = threadIdx.x; // 64 thr
    int b = bh >> 3, hh = bh & 7;
    const float* base = g_qkv + ((size_t)b*NPAD + (size_t)j*64)*QKV3 + hh*HD + dd;
    float sq = 0.f, sk = 0.f;
    for (int t = 0; t < 64; t++) {
        sq += base[(size_t)t*QKV3];
        sk += base[(size_t)t*QKV3 + D];
    }
    g_ql[((size_t)bh*M_LM + j)*HD + dd] = sq * (1.f/64.f) * 0.125f;
    g_kl[((size_t)bh*M_LM + j)*HD + dd] = sk * (1.f/64.f);
}

__global__ void k_attn2()
{
    int bh = blockIdx.y, j = blockIdx.x, t = threadIdx.x; // 256 thr
    __shared__ float qrow[64];
    __shared__ float red[256];
    if (t < 64) qrow[t] = g_ql[((size_t)bh*M_LM + j)*HD + t];
    __syncthreads();
    const float* kr = g_kl + ((size_t)bh*M_LM + t)*HD;
    float s = 0.f;
#pragma unroll
    for (int dd = 0; dd < 64; dd++) s = fmaf(qrow[dd], kr[dd], s);
    red[t] = s; __syncthreads();
    for (int st = 128; st > 0; st >>= 1) { if (t < st) red[t] = fmaxf(red[t], red[t+st]); __syncthreads(); }
    float mx = red[0]; __syncthreads();
    float e = expf(s - mx);
    red[t] = e; __syncthreads();
    for (int st = 128; st > 0; st >>= 1) { if (t < st) red[t] += red[t+st]; __syncthreads(); }
    g_a2[((size_t)bh*M_LM + j)*M_LM + t] = e / red[0];
}

__global__ void k_scale_init() { g_rmax = 0; g_cmax = 0; }

__global__ void k_scale_reduce()
{
    int bh = blockIdx.x, t = threadIdx.x; // 256 thr
    const float* a = g_a2 + (size_t)bh * M_LM * M_LM;
    float cs = 0.f, rs = 0.f;
    for (int j = 0; j < 256; j++) cs += a[(size_t)j*256 + t];
    for (int i = 0; i < 256; i++) rs += a[(size_t)t*256 + i];
    __shared__ float red[256];
    red[t] = cs; __syncthreads();
    for (int s = 128; s > 0; s >>= 1) { if (t < s) red[t] = fmaxf(red[t], red[t+s]); __syncthreads(); }
    if (t == 0) atomicMax(&g_cmax, __float_as_int(red[0]));
    __syncthreads();
    red[t] = rs; __syncthreads();
    for (int s = 128; s > 0; s >>= 1) { if (t < s) red[t] = fmaxf(red[t], red[t+s]); __syncthreads(); }
    if (t == 0) atomicMax(&g_rmax, __float_as_int(red[0]));
}

__global__ void k_zinit()
{
    int bh = blockIdx.y, i = blockIdx.x, j = threadIdx.x; // 256 thr
    float scale = __int_as_float(g_rmax) * __int_as_float(g_cmax);
    g_z0[((size_t)bh*M_LM + i)*M_LM + j] = g_a2[((size_t)bh*M_LM + j)*M_LM + i] / scale;
}

// Dst = post * X @ (diag*I + sY*Y), all 256x256 per bh
__global__ void __launch_bounds__(256) k_bmm256(
    const float* __restrict__ X, const float* __restrict__ Y,
    float* __restrict__ Dst, float diag, float sY, float post)
{
    size_t off = (size_t)blockIdx.z * M_LM * M_LM;
    X += off; Y += off; Dst += off;
    int bm = blockIdx.y * 64, bn = blockIdx.x * 64;
    __shared__ float Xs[64][33];
    __shared__ float Ys[32][65];
    int tid = threadIdx.x, ty = tid >> 4, tx = tid & 15;
    float acc[4][4] = {};
    for (int k0 = 0; k0 < 256; k0 += 32) {
        for (int idx = tid; idx < 2048; idx += 256) {
            int m = idx >> 5, kk = idx & 31;
            Xs[m][kk] = X[(size_t)(bm+m)*256 + k0 + kk];
        }
        for (int idx = tid; idx < 2048; idx += 256) {
            int kk = idx >> 6, n = idx & 63;
            int gk = k0 + kk, gn = bn + n;
            float v = sY * Y[(size_t)gk*256 + gn];
            if (gk == gn) v += diag;
            Ys[kk][n] = v;
        }
        __syncthreads();
#pragma unroll
        for (int kk = 0; kk < 32; kk++) {
            float a[4], b[4];
#pragma unroll
            for (int i = 0; i < 4; i++) a[i] = Xs[ty*4+i][kk];
#pragma unroll
            for (int j = 0; j < 4; j++) b[j] = Ys[kk][tx*4+j];
#pragma unroll
            for (int i = 0; i < 4; i++)
#pragma unroll
                for (int j = 0; j < 4; j++)
                    acc[i][j] = fmaf(a[i], b[j], acc[i][j]);
        }
        __syncthreads();
    }
#pragma unroll
    for (int i = 0; i < 4; i++)
#pragma unroll
        for (int j = 0; j < 4; j++)
            Dst[(size_t)(bm+ty*4+i)*256 + bn + tx*4+j] = post * acc[i][j];
}

// C[m,n] = alpha * A[m,:64] . B[n,:64]  (per-(b,head) strided operands)
__global__ void __launch_bounds__(256) k_gemm_k64(
    const float* __restrict__ A, long aSB, long aSH, int lda, float alpha,
    const float* __restrict__ Bp, long bSB, long bSH, int ldb,
    float* __restrict__ C, long cSB, long cSH, int ldc,
    int row0, int rowEnd)
{
    int bh = blockIdx.z, b = bh >> 3, hh = bh & 7;
    const float* Ab = A  + (size_t)b*aSB + (size_t)hh*aSH;
    const float* Bbp= Bp + (size_t)b*bSB + (size_t)hh*bSH;
    float*       Cb = C  + (size_t)b*cSB + (size_t)hh*cSH;
    int bm = row0 + blockIdx.y * 64, bn = blockIdx.x * 64;
    __shared__ float As[64][65];
    __shared__ float Bs[64][65];
    int tid = threadIdx.x;
    for (int idx = tid; idx < 4096; idx += 256) {
        int r = idx >> 6, c = idx & 63;
        As[r][c] = (bm + r < rowEnd) ? Ab[(size_t)(bm+r)*lda + c] * alpha : 0.f;
        Bs[r][c] = Bbp[(size_t)(bn+r)*ldb + c];
    }
    __syncthreads();
    int ty = tid >> 4, tx = tid & 15;
    float acc[4][4] = {};
#pragma unroll
    for (int k = 0; k < 64; k++) {
        float a[4], bb[4];
#pragma unroll
        for (int i = 0; i < 4; i++) a[i] = As[ty*4+i][k];
#pragma unroll
        for (int j = 0; j < 4; j++) bb[j] = Bs[tx*4+j][k];
#pragma unroll
        for (int i = 0; i < 4; i++)
#pragma unroll
            for (int j = 0; j < 4; j++)
                acc[i][j] = fmaf(a[i], bb[j], acc[i][j]);
    }
#pragma unroll
    for (int i = 0; i < 4; i++) {
        int row = bm + ty*4 + i;
        if (row >= rowEnd) continue;
#pragma unroll
        for (int j = 0; j < 4; j++)
            Cb[(size_t)row*ldc + bn + tx*4+j] = acc[i][j];
    }
}

__global__ void k_softmax(float* __restrict__ base, long strideBH, int row0, int N)
{
    int bh = blockIdx.y, row = row0 + blockIdx.x, t = threadIdx.x; // 256 thr
    float* p = base + (size_t)bh * strideBH + (size_t)row * N;
    __shared__ float red[256];
    float mx = -1e30f;
    for (int i = t; i < N; i += 256) mx = fmaxf(mx, p[i]);
    red[t] = mx; __syncthreads();
    for (int s = 128; s > 0; s >>= 1) { if (t < s) red[t] = fmaxf(red[t], red[t+s]); __syncthreads(); }
    mx = red[0]; __syncthreads();
    float sm = 0.f;
    for (int i = t; i < N; i += 256) { float e = expf(p[i] - mx); p[i] = e; sm += e; }
    red[t] = sm; __syncthreads();
    for (int s = 128; s > 0; s >>= 1) { if (t < s) red[t] += red[t+s]; __syncthreads(); }
    float inv = 1.f / red[0];
    for (int i = t; i < N; i += 256) p[i] *= inv;
}

// attn3(probs) @ v — split-K over 8 chunks of 2048
__global__ void __launch_bounds__(256) k_av_part()
{
    int bh = blockIdx.z, b = bh >> 3, hh = bh & 7;
    int jt = blockIdx.y, ks = blockIdx.x;
    int j0 = jt * 32;
    __shared__ float Ss[32][33];
    __shared__ float Vs[32][66];
    int tid = threadIdx.x;
    int dd = tid & 63, jq = tid >> 6;
    float acc[8] = {};
    const float* s3b = g_s3 + (size_t)bh * M_LM * NPAD;
    const float* vb  = g_qkv + (size_t)b * NPAD * QKV3 + 2*D + hh*HD;
    int i_beg = ks * 2048, i_end = i_beg + 2048;
    for (int i0 = i_beg; i0 < i_end; i0 += 32) {
        for (int idx = tid; idx < 1024; idx += 256) {
            int jj = idx >> 5, ii = idx & 31;
            Ss[jj][ii] = s3b[(size_t)(j0+jj)*NPAD + i0 + ii];
        }
        for (int idx = tid; idx < 2048; idx += 256) {
            int ii = idx >> 6, d2 = idx & 63;
            Vs[ii][d2] = vb[(size_t)(i0+ii)*QKV3 + d2];
        }
        __syncthreads();
#pragma unroll
        for (int ii = 0; ii < 32; ii++) {
            float v = Vs[ii][dd];
#pragma unroll
            for (int jj = 0; jj < 8; jj++)
                acc[jj] = fmaf(Ss[jq*8+jj][ii], v, acc[jj]);
        }
        __syncthreads();
    }
#pragma unroll
    for (int jj = 0; jj < 8; jj++)
        g_avp[(((size_t)bh*8 + ks)*M_LM + j0 + jq*8 + jj)*HD + dd] = acc[jj];
}

__global__ void k_av_reduce()
{
    int idx = blockIdx.x * 256 + threadIdx.x;
    if (idx >= BH * M_LM * HD) return;
    int bh = idx / (M_LM * HD);
    int rem = idx % (M_LM * HD);
    float s = 0.f;
    for (int ks = 0; ks < 8; ks++)
        s += g_avp[((size_t)bh*8 + ks)*M_LM*HD + rem];
    g_av[idx] = s;
}

__global__ void k_mid(const float* __restrict__ z)
{
    int bh = blockIdx.y, j = blockIdx.x, dd = threadIdx.x; // 64 thr
    const float* zr = z + ((size_t)bh*M_LM + j)*M_LM;
    const float* av = g_av + (size_t)bh*M_LM*HD;
    float s = 0.f;
    for (int t = 0; t < 256; t++) s = fmaf(zr[t], av[(size_t)t*HD + dd], s);
    g_mid[((size_t)bh*M_LM + j)*HD + dd] = s;
}

__global__ void __launch_bounds__(256) k_a1mid(int row0, int rowEnd)
{
    int bh = blockIdx.y, b = bh >> 3, hh = bh & 7;
    int bm = row0 + blockIdx.x * 64;
    __shared__ float A1s[64][33];
    __shared__ float Ms[32][66];
    const float* a1  = g_a1  + (size_t)bh * NPAD * M_LM;
    const float* mid = g_mid + (size_t)bh * M_LM * HD;
    int tid = threadIdx.x, ty = tid >> 4, tx = tid & 15;
    float acc[4][4] = {};
    for (int k0 = 0; k0 < 256; k0 += 32) {
        for (int idx = tid; idx < 2048; idx += 256) {
            int m = idx >> 5, kk = idx & 31;
            A1s[m][kk] = (bm + m < rowEnd) ? a1[(size_t)(bm+m)*M_LM + k0 + kk] : 0.f;
        }
        for (int idx = tid; idx < 2048; idx += 256) {
            int kk = idx >> 6, d2 = idx & 63;
            Ms[kk][d2] = mid[(size_t)(k0+kk)*HD + d2];
        }
        __syncthreads();
#pragma unroll
        for (int kk = 0; kk < 32; kk++) {
            float a[4], bb[4];
#pragma unroll
            for (int i = 0; i < 4; i++) a[i] = A1s[ty*4+i][kk];
#pragma unroll
            for (int j = 0; j < 4; j++) bb[j] = Ms[kk][tx*4+j];
#pragma unroll
            for (int i = 0; i < 4; i++)
#pragma unroll
                for (int j = 0; j < 4; j++)
                    acc[i][j] = fmaf(a[i], bb[j], acc[i][j]);
        }
        __syncthreads();
    }
#pragma unroll
    for (int i = 0; i < 4; i++) {
        int row = bm + ty*4 + i;
        if (row >= rowEnd) continue;
#pragma unroll
        for (int j = 0; j < 4; j++)
            g_attnout[((size_t)b*NPAD + row)*D + hh*HD + tx*4+j] = acc[i][j];
    }
}

__global__ void k_dwconv(const float* __restrict__ w, int row0, int nrows)
{
    int idx = blockIdx.x * 256 + threadIdx.x;
    int b = blockIdx.y;
    if (idx >= nrows * D) return;
    int i = row0 + idx / D;
    int col = idx % D;
    int hd = col >> 6;
    float acc = g_attnout[((size_t)b*NPAD + i)*D + col];
#pragma unroll
    for (int t = 0; t < 33; t++) {
        int ii = i + t - 16;
        if (ii >= 0 && ii < NPAD)
            acc = fmaf(w[hd*33 + t], g_qkv[((size_t)b*NPAD + ii)*QKV3 + 2*D + col], acc);
    }
    g_attnout[((size_t)b*NPAD + i)*D + col] = acc;
}

// layer-2 cls-only out-proj: clsrow = h2[b,0,:] + attnout[b,254,:] @ W^T + bias
__global__ void k_outproj_cls(const float* __restrict__ W, const float* __restrict__ bias)
{
    int b = blockIdx.x, col = threadIdx.x; // 512 thr
    const float* arow = g_attnout + ((size_t)b*NPAD + PAD0)*D;
    const float* wrow = W + (size_t)col * D;
    float acc = bias[col];
    for (int k = 0; k < 512; k++) acc = fmaf(arow[k], wrow[k], acc);
    g_clsrow[b*D + col] = g_h2[(size_t)b*NTOK*D + col] + acc;
}

__global__ void k_ppeg(const float* __restrict__ hin, float* __restrict__ hout,
                       const float* __restrict__ w7, const float* __restrict__ b7,
                       const float* __restrict__ w5, const float* __restrict__ b5,
                       const float* __restrict__ w3, const float* __restrict__ b3)
{
    int pos = blockIdx.x, b = blockIdx.y, ch = threadIdx.x; // 512 thr
    if (pos == 0)
        hout[(size_t)b*NTOK*D + ch] = hin[(size_t)b*NTOK*D + ch];
    int r = pos / HW, c = pos % HW;
    const float* fb = hin + ((size_t)b*NTOK + 1)*D + ch;
    float acc = fb[(size_t)pos*D] + b7[ch] + b5[ch] + b3[ch];
    for (int ky = 0; ky < 7; ky++) {
        int rr = r + ky - 3;
        if (rr < 0 || rr >= HW) continue;
        for (int kx = 0; kx < 7; kx++) {
            int cc = c + kx - 3;
            if (cc < 0 || cc >= HW) continue;
            float v = fb[(size_t)(rr*HW + cc)*D];
            float ws = w7[(size_t)ch*49 + ky*7 + kx];
            if (ky >= 1 && ky <= 5 && kx >= 1 && kx <= 5)
                ws += w5[(size_t)ch*25 + (ky-1)*5 + (kx-1)];
            if (ky >= 2 && ky <= 4 && kx >= 2 && kx <= 4)
                ws += w3[(size_t)ch*9 + (ky-2)*3 + (kx-2)];
            acc = fmaf(ws, v, acc);
        }
    }
    hout[((size_t)b*NTOK + 1 + pos)*D + ch] = acc;
}

__global__ void k_final(const float* __restrict__ nw, const float* __restrict__ nb,
                        const float* __restrict__ fw, const float* __restrict__ fbias,
                        float* __restrict__ out)
{
    int b = blockIdx.x, t = threadIdx.x; // 256 thr
    const float* cls = g_clsrow + (size_t)b * D;
    float x0 = cls[t], x1 = cls[t+256];
    __shared__ float red[256];
    red[t] = x0 + x1; __syncthreads();
    for (int s = 128; s > 0; s >>= 1) { if (t < s) red[t] += red[t+s]; __syncthreads(); }
    float mu = red[0] * (1.f/512.f); __syncthreads();
    float d0 = x0 - mu, d1 = x1 - mu;
    red[t] = d0*d0 + d1*d1; __syncthreads();
    for (int s = 128; s > 0; s >>= 1) { if (t < s) red[t] += red[t+s]; __syncthreads(); }
    float rs = rsqrtf(red[0] * (1.f/512.f) + LNEPS); __syncthreads();
    float n0 = d0 * rs * nw[t]     + nb[t];
    float n1 = d1 * rs * nw[t+256] + nb[t+256];
    red[t] = n0 * fw[t] + n1 * fw[t+256]; __syncthreads();
    for (int s = 128; s > 0; s >>= 1) { if (t < s) red[t] += red[t+s]; __syncthreads(); }
    float o0 = red[0] + fbias[0]; __syncthreads();
    red[t] = n0 * fw[512+t] + n1 * fw[512+t+256]; __syncthreads();
    for (int s = 128; s > 0; s >>= 1) { if (t < s) red[t] += red[t+s]; __syncthreads(); }
    float o1 = red[0] + fbias[1];
    if (t == 0) { out[b*2+0] = o0; out[b*2+1] = o1; }
}

// ---------------------------------------------------------------------------
extern "C" void kernel_launch(void* const* d_in, const int* in_sizes, int n_in,
                              void* d_out, int out_size)
{
    (void)in_sizes; (void)n_in; (void)out_size;
    const float* x       = (const float*)d_in[0];
    const float* fc1_w   = (const float*)d_in[1];
    const float* fc1_b   = (const float*)d_in[2];
    const float* cls_tok = (const float*)d_in[3];
    const float* ln_w    = (const float*)d_in[4];
    const float* ln_b    = (const float*)d_in[5];
    const float* qkv_w   = (const float*)d_in[6];
    const float* qkv_b   = (const float*)d_in[7];
    const float* aout_w  = (const float*)d_in[8];
    const float* aout_b  = (const float*)d_in[9];
    const float* res_w   = (const float*)d_in[10];
    const float* w7 = (const float*)d_in[11];
    const float* b7 = (const float*)d_in[12];
    const float* w5 = (const float*)d_in[13];
    const float* b5 = (const float*)d_in[14];
    const float* w3 = (const float*)d_in[15];
    const float* b3 = (const float*)d_in[16];
    const float* norm_w = (const float*)d_in[17];
    const float* norm_b = (const float*)d_in[18];
    const float* fc2_w  = (const float*)d_in[19];
    const float* fc2_b  = (const float*)d_in[20];
    float* out = (float*)d_out;

    float *ph, *ph2, *pxpad, *pqkv, *pz0, *pz1, *paz, *pt2, *pt4;
    cudaGetSymbolAddress((void**)&ph, g_h);
    cudaGetSymbolAddress((void**)&ph2, g_h2);
    cudaGetSymbolAddress((void**)&pxpad, g_xpad);
    cudaGetSymbolAddress((void**)&pqkv, g_qkv);
    cudaGetSymbolAddress((void**)&pz0, g_z0);
    cudaGetSymbolAddress((void**)&pz1, g_z1);
    cudaGetSymbolAddress((void**)&paz, g_az);
    cudaGetSymbolAddress((void**)&pt2, g_t2);
    cudaGetSymbolAddress((void**)&pt4, g_t4);
    float *pa2, *pql, *ps3, *pa1, *pao;
    cudaGetSymbolAddress((void**)&pa2, g_a2);
    cudaGetSymbolAddress((void**)&pql, g_ql);
    cudaGetSymbolAddress((void**)&ps3, g_s3);
    cudaGetSymbolAddress((void**)&pa1, g_a1);
    cudaGetSymbolAddress((void**)&pao, g_attnout);
    float* pkl; cudaGetSymbolAddress((void**)&pkl, g_kl);

    // fc1: h[:,1:16001] = relu(x @ fc1_w^T)
    k_sgemm<<<dim3(4, 125, Bb), 256>>>(x, fc1_w, fc1_b, ph + D,
                                       16000, D, DIN,
                                       (long)16000 * DIN, (long)NTOK * D, 1);
    k_fixup<<<dim3(130, Bb), 512>>>(cls_tok);

    for (int l = 0; l < 2; l++) {
        const float* hin = (l == 0) ? ph : ph2;
        bool clsOnly = (l == 1);

        k_lnpad<<<dim3(NPAD, Bb), 256>>>(hin, ln_w + l*D, ln_b + l*D);
        k_sgemm<<<dim3(12, 128, Bb), 256>>>(pxpad, qkv_w + (size_t)l*QKV3*D,
                                            qkv_b + l*QKV3, pqkv,
                                            NPAD, QKV3, D,
                                            (long)NPAD * D, (long)NPAD * QKV3, 0);
        k_landmarks<<<dim3(M_LM, BH), 64>>>();
        k_attn2<<<dim3(M_LM, BH), 256>>>();
        k_scale_init<<<1, 1>>>();
        k_scale_reduce<<<BH, 256>>>();
        k_zinit<<<dim3(M_LM, BH), 256>>>();

        float* zc = pz0; float* zn = pz1;
        for (int it = 0; it < 6; it++) {
            k_bmm256<<<dim3(4,4,BH), 256>>>(pa2, zc, paz, 0.f, 1.f, 1.f);
            k_bmm256<<<dim3(4,4,BH), 256>>>(paz, paz, pt2, 7.f, -1.f, 1.f);
            k_bmm256<<<dim3(4,4,BH), 256>>>(paz, pt2, pt4, 15.f, -1.f, 1.f);
            k_bmm256<<<dim3(4,4,BH), 256>>>(zc, pt4, zn, 13.f, -1.f, 0.25f);
            float* tmp = zc; zc = zn; zn = tmp;
        }
        // zc holds the final pinv

        // attn3 logits + softmax
        k_gemm_k64<<<dim3(256, 4, BH), 256>>>(
            pql, (long)8*M_LM*HD, (long)M_LM*HD, HD, 1.f,
            pqkv + D, (long)NPAD*QKV3, (long)HD, QKV3,
            ps3, (long)8*M_LM*NPAD, (long)M_LM*NPAD, NPAD, 0, M_LM);
        k_softmax<<<dim3(M_LM, BH), 256>>>(ps3, (long)M_LM*NPAD, 0, NPAD);
        k_av_part<<<dim3(8, 8, BH), 256>>>();
        k_av_reduce<<<(BH*M_LM*HD + 255)/256, 256>>>();
        k_mid<<<dim3(M_LM, BH), 64>>>(zc);

        // attn1 logits + softmax + @mid (pruned on layer 2)
        int row0 = PAD0;
        int nrows = clsOnly ? 1 : NTOK;
        int rowEnd = clsOnly ? (PAD0 + 1) : NPAD;
        int ntiles = (nrows + 63) / 64;
        k_gemm_k64<<<dim3(4, ntiles, BH), 256>>>(
            pqkv, (long)NPAD*QKV3, (long)HD, QKV3, 0.125f,
            pkl, (long)8*M_LM*HD, (long)M_LM*HD, HD,
            pa1, (long)8*NPAD*M_LM, (long)NPAD*M_LM, M_LM, row0, rowEnd);
        k_softmax<<<dim3(nrows, BH), 256>>>(pa1, (long)NPAD*M_LM, row0, M_LM);
        k_a1mid<<<dim3(ntiles, BH), 256>>>(row0, rowEnd);
        k_dwconv<<<dim3((nrows*D + 255)/256, Bb), 256>>>(res_w + l*8*33, row0, nrows);

        if (!clsOnly) {
            // h += attnout[:, 254:, :] @ aout_w^T + aout_b
            k_sgemm<<<dim3(4, (NTOK + 127)/128, Bb), 256>>>(
                pao + (size_t)PAD0 * D, aout_w + (size_t)l*D*D, aout_b + l*D, ph,
                NTOK, D, D, (long)NPAD * D, (long)NTOK * D, 2);
            k_ppeg<<<dim3(NFEAT, Bb), 512>>>(ph, ph2, w7, b7, w5, b5, w3, b3);
        } else {
            k_outproj_cls<<<Bb, 512>>>(aout_w + (size_t)l*D*D, aout_b + l*D);
        }
    }

    k_final<<<Bb, 256>>>(norm_w, norm_b, fc2_w, fc2_b, out);
}

// round 14
// speedup vs baseline: 1.1843x; 1.1843x over previous
#include <cuda_runtime.h>
#include <math.h>
#include <stdint.h>

namespace {
constexpr int Bb    = 2;
constexpr int DIN   = 1024;
constexpr int D     = 512;
constexpr int HD    = 64;
constexpr int M_LM  = 256;
constexpr int NPAD  = 16384;
constexpr int NTOK  = 16130;
constexpr int PAD0  = 254;
constexpr int BH    = 16;      // Bb * 8 heads
constexpr int QKV3  = 1536;
constexpr int HW    = 127;
constexpr int NFEAT = HW * HW; // 16129
constexpr float LNEPS = 1e-5f;
}

__device__ float g_h   [(size_t)Bb * NTOK * D];
__device__ float g_h2  [(size_t)Bb * NTOK * D];
__device__ float g_xpad[(size_t)Bb * NPAD * D];
__device__ float g_qkv [(size_t)Bb * NPAD * QKV3];
__device__ float g_ql  [(size_t)BH * M_LM * HD];
__device__ float g_kl  [(size_t)BH * M_LM * HD];
__device__ float g_a2  [(size_t)BH * M_LM * M_LM];
__device__ float g_z0  [(size_t)BH * M_LM * M_LM];
__device__ float g_z1  [(size_t)BH * M_LM * M_LM];
__device__ float g_az  [(size_t)BH * M_LM * M_LM];
__device__ float g_t2  [(size_t)BH * M_LM * M_LM];
__device__ float g_t4  [(size_t)BH * M_LM * M_LM];
__device__ float g_s3  [(size_t)BH * M_LM * NPAD];
__device__ float g_a1  [(size_t)BH * NPAD * M_LM];
__device__ float g_avp [(size_t)BH * 8 * M_LM * HD];
__device__ float g_av  [(size_t)BH * M_LM * HD];
__device__ float g_mid [(size_t)BH * M_LM * HD];
__device__ float g_attnout[(size_t)Bb * NPAD * D];
__device__ float g_clsrow[Bb * D];
__device__ int   g_rmax;
__device__ int   g_cmax;

__device__ __forceinline__ uint32_t f2tf32(float f)
{
    uint32_t u;
    asm("cvt.rna.tf32.f32 %0, %1;" : "=r"(u) : "f"(f));
    return u;
}

__device__ __forceinline__ void mma_tf32(float* c, const uint32_t* a, const uint32_t* b)
{
    asm volatile(
        "mma.sync.aligned.m16n8k8.row.col.f32.tf32.tf32.f32 "
        "{%0,%1,%2,%3}, {%4,%5,%6,%7}, {%8,%9}, {%0,%1,%2,%3};\n"
        : "+f"(c[0]), "+f"(c[1]), "+f"(c[2]), "+f"(c[3])
        : "r"(a[0]), "r"(a[1]), "r"(a[2]), "r"(a[3]),
          "r"(b[0]), "r"(b[1]));
}

// ---------------- dense GEMM (tf32 tensor core): C = A(MxK) * W(NxK)^T ------
// epi: 0 store, 1 relu-store, 2 accumulate (C += acc+bias)
// BM=128 BN=128 BK=16, 256 threads (8 warps), warp tile 64x32 via m16n8k8.
__global__ void __launch_bounds__(256) k_sgemm(
    const float* __restrict__ A, const float* __restrict__ W,
    const float* __restrict__ bias, float* __restrict__ C,
    int M, int N, int K, long strideA, long strideC, int epi)
{
    const float* Ab = A + (size_t)blockIdx.z * strideA;
    float*       Cb = C + (size_t)blockIdx.z * strideC;
    int bm = blockIdx.y * 128, bn = blockIdx.x * 128;
    __shared__ float As[16][136];
    __shared__ float Ws[16][136];
    int tid  = threadIdx.x;
    int warp = tid >> 5, lane = tid & 31;
    int wm = (warp & 1) * 64;        // warp row origin within block tile
    int wn = (warp >> 1) * 32;       // warp col origin within block tile
    int grp = lane >> 2, tig = lane & 3;
    int lr = tid & 127, lc = (tid >> 7) * 8;  // loader mapping: 1 row, 8 cols

    float acc[4][4][4];
#pragma unroll
    for (int mt = 0; mt < 4; mt++)
#pragma unroll
        for (int nt = 0; nt < 4; nt++)
#pragma unroll
            for (int r = 0; r < 4; r++) acc[mt][nt][r] = 0.f;

    for (int k0 = 0; k0 < K; k0 += 16) {
        float4 a0v = make_float4(0.f,0.f,0.f,0.f);
        float4 a1v = make_float4(0.f,0.f,0.f,0.f);
        if (bm + lr < M) {
            a0v = *(const float4*)&Ab[(size_t)(bm + lr) * K + k0 + lc];
            a1v = *(const float4*)&Ab[(size_t)(bm + lr) * K + k0 + lc + 4];
        }
        float4 w0v = *(const float4*)&W[(size_t)(bn + lr) * K + k0 + lc];
        float4 w1v = *(const float4*)&W[(size_t)(bn + lr) * K + k0 + lc + 4];
        As[lc+0][lr]=a0v.x; As[lc+1][lr]=a0v.y; As[lc+2][lr]=a0v.z; As[lc+3][lr]=a0v.w;
        As[lc+4][lr]=a1v.x; As[lc+5][lr]=a1v.y; As[lc+6][lr]=a1v.z; As[lc+7][lr]=a1v.w;
        Ws[lc+0][lr]=w0v.x; Ws[lc+1][lr]=w0v.y; Ws[lc+2][lr]=w0v.z; Ws[lc+3][lr]=w0v.w;
        Ws[lc+4][lr]=w1v.x; Ws[lc+5][lr]=w1v.y; Ws[lc+6][lr]=w1v.z; Ws[lc+7][lr]=w1v.w;
        __syncthreads();

#pragma unroll
        for (int ks = 0; ks < 16; ks += 8) {
            uint32_t af[4][4];
            uint32_t bf[4][2];
#pragma unroll
            for (int mt = 0; mt < 4; mt++) {
                int mb = wm + mt * 16;
                af[mt][0] = f2tf32(As[ks + tig    ][mb + grp    ]);
                af[mt][1] = f2tf32(As[ks + tig    ][mb + grp + 8]);
                af[mt][2] = f2tf32(As[ks + tig + 4][mb + grp    ]);
                af[mt][3] = f2tf32(As[ks + tig + 4][mb + grp + 8]);
            }
#pragma unroll
            for (int nt = 0; nt < 4; nt++) {
                int nb = wn + nt * 8;
                bf[nt][0] = f2tf32(Ws[ks + tig    ][nb + grp]);
                bf[nt][1] = f2tf32(Ws[ks + tig + 4][nb + grp]);
            }
#pragma unroll
            for (int mt = 0; mt < 4; mt++)
#pragma unroll
                for (int nt = 0; nt < 4; nt++)
                    mma_tf32(acc[mt][nt], af[mt], bf[nt]);
        }
        __syncthreads();
    }

    // epilogue: c0:(grp,2*tig) c1:(grp,2*tig+1) c2:(grp+8,2*tig) c3:(grp+8,2*tig+1)
#pragma unroll
    for (int mt = 0; mt < 4; mt++) {
#pragma unroll
        for (int nt = 0; nt < 4; nt++) {
            int row0 = bm + wm + mt * 16 + grp;
            int col0 = bn + wn + nt * 8 + tig * 2;
            float b0 = bias[col0], b1 = bias[col0 + 1];
            if (row0 < M) {
                float v0 = acc[mt][nt][0] + b0;
                float v1 = acc[mt][nt][1] + b1;
                size_t i0 = (size_t)row0 * N + col0;
                if (epi == 1) { v0 = fmaxf(v0, 0.f); v1 = fmaxf(v1, 0.f); }
                if (epi == 2) { Cb[i0] += v0; Cb[i0 + 1] += v1; }
                else          { Cb[i0]  = v0; Cb[i0 + 1]  = v1; }
            }
            if (row0 + 8 < M) {
                float v2 = acc[mt][nt][2] + b0;
                float v3 = acc[mt][nt][3] + b1;
                size_t i2 = (size_t)(row0 + 8) * N + col0;
                if (epi == 1) { v2 = fmaxf(v2, 0.f); v3 = fmaxf(v3, 0.f); }
                if (epi == 2) { Cb[i2] += v2; Cb[i2 + 1] += v3; }
                else          { Cb[i2]  = v2; Cb[i2 + 1]  = v3; }
            }
        }
    }
}

// cls token into row 0, wrap rows 16001..16129 from rows 1..129
__global__ void k_fixup(const float* __restrict__ cls)
{
    int b = blockIdx.y, r = blockIdx.x, c = threadIdx.x; // 512 thr
    if (r == 0) g_h[(size_t)b * NTOK * D + c] = cls[c];
    else {
        int j = r - 1;
        g_h[((size_t)b*NTOK + 16001 + j)*D + c] = g_h[((size_t)b*NTOK + 1 + j)*D + c];
    }
}

__global__ void k_lnpad(const float* __restrict__ hin,
                        const float* __restrict__ w, const float* __restrict__ b)
{
    int row = blockIdx.x, bb = blockIdx.y, t = threadIdx.x; // 256 thr
    float* out = g_xpad + ((size_t)bb * NPAD + row) * D;
    if (row < PAD0) { out[t] = 0.f; out[t+256] = 0.f; return; }
    const float* in = hin + ((size_t)bb * NTOK + row - PAD0) * D;
    float x0 = in[t], x1 = in[t+256];
    __shared__ float red[256];
    red[t] = x0 + x1; __syncthreads();
    for (int s = 128; s > 0; s >>= 1) { if (t < s) red[t] += red[t+s]; __syncthreads(); }
    float mu = red[0] * (1.f/512.f); __syncthreads();
    float d0 = x0 - mu, d1 = x1 - mu;
    red[t] = d0*d0 + d1*d1; __syncthreads();
    for (int s = 128; s > 0; s >>= 1) { if (t < s) red[t] += red[t+s]; __syncthreads(); }
    float rs = rsqrtf(red[0] * (1.f/512.f) + LNEPS);
    out[t]     = d0 * rs * w[t]     + b[t];
    out[t+256] = d1 * rs * w[t+256] + b[t+256];
}

__global__ void k_landmarks()
{
    int bh = blockIdx.y, j = blockIdx.x, dd = threadIdx.x; // 64 thr
    int b = bh >> 3, hh = bh & 7;
    const float* base = g_qkv + ((size_t)b*NPAD + (size_t)j*64)*QKV3 + hh*HD + dd;
    float sq = 0.f, sk = 0.f;
    for (int t = 0; t < 64; t++) {
        sq += base[(size_t)t*QKV3];
        sk += base[(size_t)t*QKV3 + D];
    }
    g_ql[((size_t)bh*M_LM + j)*HD + dd] = sq * (1.f/64.f) * 0.125f;
    g_kl[((size_t)bh*M_LM + j)*HD + dd] = sk * (1.f/64.f);
}

__global__ void k_attn2()
{
    int bh = blockIdx.y, j = blockIdx.x, t = threadIdx.x; // 256 thr
    __shared__ float qrow[64];
    __shared__ float red[256];
    if (t < 64) qrow[t] = g_ql[((size_t)bh*M_LM + j)*HD + t];
    __syncthreads();
    const float* kr = g_kl + ((size_t)bh*M_LM + t)*HD;
    float s = 0.f;
#pragma unroll
    for (int dd = 0; dd < 64; dd++) s = fmaf(qrow[dd], kr[dd], s);
    red[t] = s; __syncthreads();
    for (int st = 128; st > 0; st >>= 1) { if (t < st) red[t] = fmaxf(red[t], red[t+st]); __syncthreads(); }
    float mx = red[0]; __syncthreads();
    float e = expf(s - mx);
    red[t] = e; __syncthreads();
    for (int st = 128; st > 0; st >>= 1) { if (t < st) red[t] += red[t+st]; __syncthreads(); }
    g_a2[((size_t)bh*M_LM + j)*M_LM + t] = e / red[0];
}

__global__ void k_scale_init() { g_rmax = 0; g_cmax = 0; }

__global__ void k_scale_reduce()
{
    int bh = blockIdx.x, t = threadIdx.x; // 256 thr
    const float* a = g_a2 + (size_t)bh * M_LM * M_LM;
    float cs = 0.f, rs = 0.f;
    for (int j = 0; j < 256; j++) cs += a[(size_t)j*256 + t];
    for (int i = 0; i < 256; i++) rs += a[(size_t)t*256 + i];
    __shared__ float red[256];
    red[t] = cs; __syncthreads();
    for (int s = 128; s > 0; s >>= 1) { if (t < s) red[t] = fmaxf(red[t], red[t+s]); __syncthreads(); }
    if (t == 0) atomicMax(&g_cmax, __float_as_int(red[0]));
    __syncthreads();
    red[t] = rs; __syncthreads();
    for (int s = 128; s > 0; s >>= 1) { if (t < s) red[t] = fmaxf(red[t], red[t+s]); __syncthreads(); }
    if (t == 0) atomicMax(&g_rmax, __float_as_int(red[0]));
}

__global__ void k_zinit()
{
    int bh = blockIdx.y, i = blockIdx.x, j = threadIdx.x; // 256 thr
    float scale = __int_as_float(g_rmax) * __int_as_float(g_cmax);
    g_z0[((size_t)bh*M_LM + i)*M_LM + j] = g_a2[((size_t)bh*M_LM + j)*M_LM + i] / scale;
}

// Dst = post * X @ (diag*I + sY*Y), all 256x256 per bh
__global__ void __launch_bounds__(256) k_bmm256(
    const float* __restrict__ X, const float* __restrict__ Y,
    float* __restrict__ Dst, float diag, float sY, float post)
{
    size_t off = (size_t)blockIdx.z * M_LM * M_LM;
    X += off; Y += off; Dst += off;
    int bm = blockIdx.y * 64, bn = blockIdx.x * 64;
    __shared__ float Xs[64][33];
    __shared__ float Ys[32][65];
    int tid = threadIdx.x, ty = tid >> 4, tx = tid & 15;
    float acc[4][4] = {};
    for (int k0 = 0; k0 < 256; k0 += 32) {
        for (int idx = tid; idx < 2048; idx += 256) {
            int m = idx >> 5, kk = idx & 31;
            Xs[m][kk] = X[(size_t)(bm+m)*256 + k0 + kk];
        }
        for (int idx = tid; idx < 2048; idx += 256) {
            int kk = idx >> 6, n = idx & 63;
            int gk = k0 + kk, gn = bn + n;
            float v = sY * Y[(size_t)gk*256 + gn];
            if (gk == gn) v += diag;
            Ys[kk][n] = v;
        }
        __syncthreads();
#pragma unroll
        for (int kk = 0; kk < 32; kk++) {
            float a[4], b[4];
#pragma unroll
            for (int i = 0; i < 4; i++) a[i] = Xs[ty*4+i][kk];
#pragma unroll
            for (int j = 0; j < 4; j++) b[j] = Ys[kk][tx*4+j];
#pragma unroll
            for (int i = 0; i < 4; i++)
#pragma unroll
                for (int j = 0; j < 4; j++)
                    acc[i][j] = fmaf(a[i], b[j], acc[i][j]);
        }
        __syncthreads();
    }
#pragma unroll
    for (int i = 0; i < 4; i++)
#pragma unroll
        for (int j = 0; j < 4; j++)
            Dst[(size_t)(bm+ty*4+i)*256 + bn + tx*4+j] = post * acc[i][j];
}

// C[m,n] = alpha * A[m,:64] . B[n,:64]  (per-(b,head) strided operands)
__global__ void __launch_bounds__(256) k_gemm_k64(
    const float* __restrict__ A, long aSB, long aSH, int lda, float alpha,
    const float* __restrict__ Bp, long bSB, long bSH, int ldb,
    float* __restrict__ C, long cSB, long cSH, int ldc,
    int row0, int rowEnd)
{
    int bh = blockIdx.z, b = bh >> 3, hh = bh & 7;
    const float* Ab = A  + (size_t)b*aSB + (size_t)hh*aSH;
    const float* Bbp= Bp + (size_t)b*bSB + (size_t)hh*bSH;
    float*       Cb = C  + (size_t)b*cSB + (size_t)hh*cSH;
    int bm = row0 + blockIdx.y * 64, bn = blockIdx.x * 64;
    __shared__ float As[64][65];
    __shared__ float Bs[64][65];
    int tid = threadIdx.x;
    for (int idx = tid; idx < 4096; idx += 256) {
        int r = idx >> 6, c = idx & 63;
        As[r][c] = (bm + r < rowEnd) ? Ab[(size_t)(bm+r)*lda + c] * alpha : 0.f;
        Bs[r][c] = Bbp[(size_t)(bn+r)*ldb + c];
    }
    __syncthreads();
    int ty = tid >> 4, tx = tid & 15;
    float acc[4][4] = {};
#pragma unroll
    for (int k = 0; k < 64; k++) {
        float a[4], bb[4];
#pragma unroll
        for (int i = 0; i < 4; i++) a[i] = As[ty*4+i][k];
#pragma unroll
        for (int j = 0; j < 4; j++) bb[j] = Bs[tx*4+j][k];
#pragma unroll
        for (int i = 0; i < 4; i++)
#pragma unroll
            for (int j = 0; j < 4; j++)
                acc[i][j] = fmaf(a[i], bb[j], acc[i][j]);
    }
#pragma unroll
    for (int i = 0; i < 4; i++) {
        int row = bm + ty*4 + i;
        if (row >= rowEnd) continue;
#pragma unroll
        for (int j = 0; j < 4; j++)
            Cb[(size_t)row*ldc + bn + tx*4+j] = acc[i][j];
    }
}

__global__ void k_softmax(float* __restrict__ base, long strideBH, int row0, int N)
{
    int bh = blockIdx.y, row = row0 + blockIdx.x, t = threadIdx.x; // 256 thr
    float* p = base + (size_t)bh * strideBH + (size_t)row * N;
    __shared__ float red[256];
    float mx = -1e30f;
    for (int i = t; i < N; i += 256) mx = fmaxf(mx, p[i]);
    red[t] = mx; __syncthreads();
    for (int s = 128; s > 0; s >>= 1) { if (t < s) red[t] = fmaxf(red[t], red[t+s]); __syncthreads(); }
    mx = red[0]; __syncthreads();
    float sm = 0.f;
    for (int i = t; i < N; i += 256) { float e = expf(p[i] - mx); p[i] = e; sm += e; }
    red[t] = sm; __syncthreads();
    for (int s = 128; s > 0; s >>= 1) { if (t < s) red[t] += red[t+s]; __syncthreads(); }
    float inv = 1.f / red[0];
    for (int i = t; i < N; i += 256) p[i] *= inv;
}

// attn3(probs) @ v — split-K over 8 chunks of 2048
__global__ void __launch_bounds__(256) k_av_part()
{
    int bh = blockIdx.z, b = bh >> 3, hh = bh & 7;
    int jt = blockIdx.y, ks = blockIdx.x;
    int j0 = jt * 32;
    __shared__ float Ss[32][33];
    __shared__ float Vs[32][66];
    int tid = threadIdx.x;
    int dd = tid & 63, jq = tid >> 6;
    float acc[8] = {};
    const float* s3b = g_s3 + (size_t)bh * M_LM * NPAD;
    const float* vb  = g_qkv + (size_t)b * NPAD * QKV3 + 2*D + hh*HD;
    int i_beg = ks * 2048, i_end = i_beg + 2048;
    for (int i0 = i_beg; i0 < i_end; i0 += 32) {
        for (int idx = tid; idx < 1024; idx += 256) {
            int jj = idx >> 5, ii = idx & 31;
            Ss[jj][ii] = s3b[(size_t)(j0+jj)*NPAD + i0 + ii];
        }
        for (int idx = tid; idx < 2048; idx += 256) {
            int ii = idx >> 6, d2 = idx & 63;
            Vs[ii][d2] = vb[(size_t)(i0+ii)*QKV3 + d2];
        }
        __syncthreads();
#pragma unroll
        for (int ii = 0; ii < 32; ii++) {
            float v = Vs[ii][dd];
#pragma unroll
            for (int jj = 0; jj < 8; jj++)
                acc[jj] = fmaf(Ss[jq*8+jj][ii], v, acc[jj]);
        }
        __syncthreads();
    }
#pragma unroll
    for (int jj = 0; jj < 8; jj++)
        g_avp[(((size_t)bh*8 + ks)*M_LM + j0 + jq*8 + jj)*HD + dd] = acc[jj];
}

__global__ void k_av_reduce()
{
    int idx = blockIdx.x * 256 + threadIdx.x;
    if (idx >= BH * M_LM * HD) return;
    int bh = idx / (M_LM * HD);
    int rem = idx % (M_LM * HD);
    float s = 0.f;
    for (int ks = 0; ks < 8; ks++)
        s += g_avp[((size_t)bh*8 + ks)*M_LM*HD + rem];
    g_av[idx] = s;
}

__global__ void k_mid(const float* __restrict__ z)
{
    int bh = blockIdx.y, j = blockIdx.x, dd = threadIdx.x; // 64 thr
    const float* zr = z + ((size_t)bh*M_LM + j)*M_LM;
    const float* av = g_av + (size_t)bh*M_LM*HD;
    float s = 0.f;
    for (int t = 0; t < 256; t++) s = fmaf(zr[t], av[(size_t)t*HD + dd], s);
    g_mid[((size_t)bh*M_LM + j)*HD + dd] = s;
}

__global__ void __launch_bounds__(256) k_a1mid(int row0, int rowEnd)
{
    int bh = blockIdx.y, b = bh >> 3, hh = bh & 7;
    int bm = row0 + blockIdx.x * 64;
    __shared__ float A1s[64][33];
    __shared__ float Ms[32][66];
    const float* a1  = g_a1  + (size_t)bh * NPAD * M_LM;
    const float* mid = g_mid + (size_t)bh * M_LM * HD;
    int tid = threadIdx.x, ty = tid >> 4, tx = tid & 15;
    float acc[4][4] = {};
    for (int k0 = 0; k0 < 256; k0 += 32) {
        for (int idx = tid; idx < 2048; idx += 256) {
            int m = idx >> 5, kk = idx & 31;
            A1s[m][kk] = (bm + m < rowEnd) ? a1[(size_t)(bm+m)*M_LM + k0 + kk] : 0.f;
        }
        for (int idx = tid; idx < 2048; idx += 256) {
            int kk = idx >> 6, d2 = idx & 63;
            Ms[kk][d2] = mid[(size_t)(k0+kk)*HD + d2];
        }
        __syncthreads();
#pragma unroll
        for (int kk = 0; kk < 32; kk++) {
            float a[4], bb[4];
#pragma unroll
            for (int i = 0; i < 4; i++) a[i] = A1s[ty*4+i][kk];
#pragma unroll
            for (int j = 0; j < 4; j++) bb[j] = Ms[kk][tx*4+j];
#pragma unroll
            for (int i = 0; i < 4; i++)
#pragma unroll
                for (int j = 0; j < 4; j++)
                    acc[i][j] = fmaf(a[i], bb[j], acc[i][j]);
        }
        __syncthreads();
    }
#pragma unroll
    for (int i = 0; i < 4; i++) {
        int row = bm + ty*4 + i;
        if (row >= rowEnd) continue;
#pragma unroll
        for (int j = 0; j < 4; j++)
            g_attnout[((size_t)b*NPAD + row)*D + hh*HD + tx*4+j] = acc[i][j];
    }
}

__global__ void k_dwconv(const float* __restrict__ w, int row0, int nrows)
{
    int idx = blockIdx.x * 256 + threadIdx.x;
    int b = blockIdx.y;
    if (idx >= nrows * D) return;
    int i = row0 + idx / D;
    int col = idx % D;
    int hd = col >> 6;
    float acc = g_attnout[((size_t)b*NPAD + i)*D + col];
#pragma unroll
    for (int t = 0; t < 33; t++) {
        int ii = i + t - 16;
        if (ii >= 0 && ii < NPAD)
            acc = fmaf(w[hd*33 + t], g_qkv[((size_t)b*NPAD + ii)*QKV3 + 2*D + col], acc);
    }
    g_attnout[((size_t)b*NPAD + i)*D + col] = acc;
}

// layer-2 cls-only out-proj: clsrow = h2[b,0,:] + attnout[b,254,:] @ W^T + bias
__global__ void k_outproj_cls(const float* __restrict__ W, const float* __restrict__ bias)
{
    int b = blockIdx.x, col = threadIdx.x; // 512 thr
    const float* arow = g_attnout + ((size_t)b*NPAD + PAD0)*D;
    const float* wrow = W + (size_t)col * D;
    float acc = bias[col];
    for (int k = 0; k < 512; k++) acc = fmaf(arow[k], wrow[k], acc);
    g_clsrow[b*D + col] = g_h2[(size_t)b*NTOK*D + col] + acc;
}

__global__ void k_ppeg(const float* __restrict__ hin, float* __restrict__ hout,
                       const float* __restrict__ w7, const float* __restrict__ b7,
                       const float* __restrict__ w5, const float* __restrict__ b5,
                       const float* __restrict__ w3, const float* __restrict__ b3)
{
    int pos = blockIdx.x, b = blockIdx.y, ch = threadIdx.x; // 512 thr
    if (pos == 0)
        hout[(size_t)b*NTOK*D + ch] = hin[(size_t)b*NTOK*D + ch];
    int r = pos / HW, c = pos % HW;
    const float* fb = hin + ((size_t)b*NTOK + 1)*D + ch;
    float acc = fb[(size_t)pos*D] + b7[ch] + b5[ch] + b3[ch];
    for (int ky = 0; ky < 7; ky++) {
        int rr = r + ky - 3;
        if (rr < 0 || rr >= HW) continue;
        for (int kx = 0; kx < 7; kx++) {
            int cc = c + kx - 3;
            if (cc < 0 || cc >= HW) continue;
            float v = fb[(size_t)(rr*HW + cc)*D];
            float ws = w7[(size_t)ch*49 + ky*7 + kx];
            if (ky >= 1 && ky <= 5 && kx >= 1 && kx <= 5)
                ws += w5[(size_t)ch*25 + (ky-1)*5 + (kx-1)];
            if (ky >= 2 && ky <= 4 && kx >= 2 && kx <= 4)
                ws += w3[(size_t)ch*9 + (ky-2)*3 + (kx-2)];
            acc = fmaf(ws, v, acc);
        }
    }
    hout[((size_t)b*NTOK + 1 + pos)*D + ch] = acc;
}

__global__ void k_final(const float* __restrict__ nw, const float* __restrict__ nb,
                        const float* __restrict__ fw, const float* __restrict__ fbias,
                        float* __restrict__ out)
{
    int b = blockIdx.x, t = threadIdx.x; // 256 thr
    const float* cls = g_clsrow + (size_t)b * D;
    float x0 = cls[t], x1 = cls[t+256];
    __shared__ float red[256];
    red[t] = x0 + x1; __syncthreads();
    for (int s = 128; s > 0; s >>= 1) { if (t < s) red[t] += red[t+s]; __syncthreads(); }
    float mu = red[0] * (1.f/512.f); __syncthreads();
    float d0 = x0 - mu, d1 = x1 - mu;
    red[t] = d0*d0 + d1*d1; __syncthreads();
    for (int s = 128; s > 0; s >>= 1) { if (t < s) red[t] += red[t+s]; __syncthreads(); }
    float rs = rsqrtf(red[0] * (1.f/512.f) + LNEPS); __syncthreads();
    float n0 = d0 * rs * nw[t]     + nb[t];
    float n1 = d1 * rs * nw[t+256] + nb[t+256];
    red[t] = n0 * fw[t] + n1 * fw[t+256]; __syncthreads();
    for (int s = 128; s > 0; s >>= 1) { if (t < s) red[t] += red[t+s]; __syncthreads(); }
    float o0 = red[0] + fbias[0]; __syncthreads();
    red[t] = n0 * fw[512+t] + n1 * fw[512+t+256]; __syncthreads();
    for (int s = 128; s > 0; s >>= 1) { if (t < s) red[t] += red[t+s]; __syncthreads(); }
    float o1 = red[0] + fbias[1];
    if (t == 0) { out[b*2+0] = o0; out[b*2+1] = o1; }
}

// ---------------------------------------------------------------------------
extern "C" void kernel_launch(void* const* d_in, const int* in_sizes, int n_in,
                              void* d_out, int out_size)
{
    (void)in_sizes; (void)n_in; (void)out_size;
    const float* x       = (const float*)d_in[0];
    const float* fc1_w   = (const float*)d_in[1];
    const float* fc1_b   = (const float*)d_in[2];
    const float* cls_tok = (const float*)d_in[3];
    const float* ln_w    = (const float*)d_in[4];
    const float* ln_b    = (const float*)d_in[5];
    const float* qkv_w   = (const float*)d_in[6];
    const float* qkv_b   = (const float*)d_in[7];
    const float* aout_w  = (const float*)d_in[8];
    const float* aout_b  = (const float*)d_in[9];
    const float* res_w   = (const float*)d_in[10];
    const float* w7 = (const float*)d_in[11];
    const float* b7 = (const float*)d_in[12];
    const float* w5 = (const float*)d_in[13];
    const float* b5 = (const float*)d_in[14];
    const float* w3 = (const float*)d_in[15];
    const float* b3 = (const float*)d_in[16];
    const float* norm_w = (const float*)d_in[17];
    const float* norm_b = (const float*)d_in[18];
    const float* fc2_w  = (const float*)d_in[19];
    const float* fc2_b  = (const float*)d_in[20];
    float* out = (float*)d_out;

    float *ph, *ph2, *pxpad, *pqkv, *pz0, *pz1, *paz, *pt2, *pt4;
    cudaGetSymbolAddress((void**)&ph, g_h);
    cudaGetSymbolAddress((void**)&ph2, g_h2);
    cudaGetSymbolAddress((void**)&pxpad, g_xpad);
    cudaGetSymbolAddress((void**)&pqkv, g_qkv);
    cudaGetSymbolAddress((void**)&pz0, g_z0);
    cudaGetSymbolAddress((void**)&pz1, g_z1);
    cudaGetSymbolAddress((void**)&paz, g_az);
    cudaGetSymbolAddress((void**)&pt2, g_t2);
    cudaGetSymbolAddress((void**)&pt4, g_t4);
    float *pa2, *pql, *ps3, *pa1, *pao;
    cudaGetSymbolAddress((void**)&pa2, g_a2);
    cudaGetSymbolAddress((void**)&pql, g_ql);
    cudaGetSymbolAddress((void**)&ps3, g_s3);
    cudaGetSymbolAddress((void**)&pa1, g_a1);
    cudaGetSymbolAddress((void**)&pao, g_attnout);
    float* pkl; cudaGetSymbolAddress((void**)&pkl, g_kl);

    // fc1: h[:,1:16001] = relu(x @ fc1_w^T)
    k_sgemm<<<dim3(4, 125, Bb), 256>>>(x, fc1_w, fc1_b, ph + D,
                                       16000, D, DIN,
                                       (long)16000 * DIN, (long)NTOK * D, 1);
    k_fixup<<<dim3(130, Bb), 512>>>(cls_tok);

    for (int l = 0; l < 2; l++) {
        const float* hin = (l == 0) ? ph : ph2;
        bool clsOnly = (l == 1);

        k_lnpad<<<dim3(NPAD, Bb), 256>>>(hin, ln_w + l*D, ln_b + l*D);
        k_sgemm<<<dim3(12, 128, Bb), 256>>>(pxpad, qkv_w + (size_t)l*QKV3*D,
                                            qkv_b + l*QKV3, pqkv,
                                            NPAD, QKV3, D,
                                            (long)NPAD * D, (long)NPAD * QKV3, 0);
        k_landmarks<<<dim3(M_LM, BH), 64>>>();
        k_attn2<<<dim3(M_LM, BH), 256>>>();
        k_scale_init<<<1, 1>>>();
        k_scale_reduce<<<BH, 256>>>();
        k_zinit<<<dim3(M_LM, BH), 256>>>();

        float* zc = pz0; float* zn = pz1;
        for (int it = 0; it < 6; it++) {
            k_bmm256<<<dim3(4,4,BH), 256>>>(pa2, zc, paz, 0.f, 1.f, 1.f);
            k_bmm256<<<dim3(4,4,BH), 256>>>(paz, paz, pt2, 7.f, -1.f, 1.f);
            k_bmm256<<<dim3(4,4,BH), 256>>>(paz, pt2, pt4, 15.f, -1.f, 1.f);
            k_bmm256<<<dim3(4,4,BH), 256>>>(zc, pt4, zn, 13.f, -1.f, 0.25f);
            float* tmp = zc; zc = zn; zn = tmp;
        }
        // zc holds the final pinv

        // attn3 logits + softmax
        k_gemm_k64<<<dim3(256, 4, BH), 256>>>(
            pql, (long)8*M_LM*HD, (long)M_LM*HD, HD, 1.f,
            pqkv + D, (long)NPAD*QKV3, (long)HD, QKV3,
            ps3, (long)8*M_LM*NPAD, (long)M_LM*NPAD, NPAD, 0, M_LM);
        k_softmax<<<dim3(M_LM, BH), 256>>>(ps3, (long)M_LM*NPAD, 0, NPAD);
        k_av_part<<<dim3(8, 8, BH), 256>>>();
        k_av_reduce<<<(BH*M_LM*HD + 255)/256, 256>>>();
        k_mid<<<dim3(M_LM, BH), 64>>>(zc);

        // attn1 logits + softmax + @mid (pruned on layer 2)
        int row0 = PAD0;
        int nrows = clsOnly ? 1 : NTOK;
        int rowEnd = clsOnly ? (PAD0 + 1) : NPAD;
        int ntiles = (nrows + 63) / 64;
        k_gemm_k64<<<dim3(4, ntiles, BH), 256>>>(
            pqkv, (long)NPAD*QKV3, (long)HD, QKV3, 0.125f,
            pkl, (long)8*M_LM*HD, (long)M_LM*HD, HD,
            pa1, (long)8*NPAD*M_LM, (long)NPAD*M_LM, M_LM, row0, rowEnd);
        k_softmax<<<dim3(nrows, BH), 256>>>(pa1, (long)NPAD*M_LM, row0, M_LM);
        k_a1mid<<<dim3(ntiles, BH), 256>>>(row0, rowEnd);
        k_dwconv<<<dim3((nrows*D + 255)/256, Bb), 256>>>(res_w + l*8*33, row0, nrows);

        if (!clsOnly) {
            // h += attnout[:, 254:, :] @ aout_w^T + aout_b
            k_sgemm<<<dim3(4, (NTOK + 127)/128, Bb), 256>>>(
                pao + (size_t)PAD0 * D, aout_w + (size_t)l*D*D, aout_b + l*D, ph,
                NTOK, D, D, (long)NPAD * D, (long)NTOK * D, 2);
            k_ppeg<<<dim3(NFEAT, Bb), 512>>>(ph, ph2, w7, b7, w5, b5, w3, b3);
        } else {
            k_outproj_cls<<<Bb, 512>>>(aout_w + (size_t)l*D*D, aout_b + l*D);
        }
    }

    k_final<<<Bb, 256>>>(norm_w, norm_b, fc2_w, fc2_b, out);
}

// round 16
// speedup vs baseline: 1.3315x; 1.1243x over previous
#include <cuda_runtime.h>
#include <math.h>
#include <stdint.h>

namespace {
constexpr int Bb    = 2;
constexpr int DIN   = 1024;
constexpr int D     = 512;
constexpr int HD    = 64;
constexpr int M_LM  = 256;
constexpr int NPAD  = 16384;
constexpr int NTOK  = 16130;
constexpr int PAD0  = 254;
constexpr int BH    = 16;      // Bb * 8 heads
constexpr int QKV3  = 1536;
constexpr int HW    = 127;
constexpr int NFEAT = HW * HW; // 16129
constexpr float LNEPS = 1e-5f;
}

__device__ float g_h   [(size_t)Bb * NTOK * D];
__device__ float g_h2  [(size_t)Bb * NTOK * D];
__device__ float g_xpad[(size_t)Bb * NPAD * D];
__device__ float g_qkv [(size_t)Bb * NPAD * QKV3];
__device__ float g_ql  [(size_t)BH * M_LM * HD];
__device__ float g_kl  [(size_t)BH * M_LM * HD];
__device__ float g_a2  [(size_t)BH * M_LM * M_LM];
__device__ float g_z0  [(size_t)BH * M_LM * M_LM];
__device__ float g_z1  [(size_t)BH * M_LM * M_LM];
__device__ float g_az  [(size_t)BH * M_LM * M_LM];
__device__ float g_t2  [(size_t)BH * M_LM * M_LM];
__device__ float g_t4  [(size_t)BH * M_LM * M_LM];
__device__ float g_s3  [(size_t)BH * M_LM * NPAD];
__device__ float g_a1  [(size_t)BH * NPAD * M_LM];
__device__ float g_avp [(size_t)BH * 8 * M_LM * HD];
__device__ float g_av  [(size_t)BH * M_LM * HD];
__device__ float g_mid [(size_t)BH * M_LM * HD];
__device__ float g_attnout[(size_t)Bb * NPAD * D];
__device__ float g_clsrow[Bb * D];
__device__ int   g_rmax;
__device__ int   g_cmax;

__device__ __forceinline__ uint32_t f2tf32(float f)
{
    uint32_t u;
    asm("cvt.rna.tf32.f32 %0, %1;" : "=r"(u) : "f"(f));
    return u;
}

__device__ __forceinline__ void mma_tf32(float* c, const uint32_t* a, const uint32_t* b)
{
    asm volatile(
        "mma.sync.aligned.m16n8k8.row.col.f32.tf32.tf32.f32 "
        "{%0,%1,%2,%3}, {%4,%5,%6,%7}, {%8,%9}, {%0,%1,%2,%3};\n"
        : "+f"(c[0]), "+f"(c[1]), "+f"(c[2]), "+f"(c[3])
        : "r"(a[0]), "r"(a[1]), "r"(a[2]), "r"(a[3]),
          "r"(b[0]), "r"(b[1]));
}

// ---------------- dense GEMM (tf32 tensor core): C = A(MxK) * W(NxK)^T ------
// epi: 0 store, 1 relu-store, 2 accumulate (C += acc+bias)
__global__ void __launch_bounds__(256) k_sgemm(
    const float* __restrict__ A, const float* __restrict__ W,
    const float* __restrict__ bias, float* __restrict__ C,
    int M, int N, int K, long strideA, long strideC, int epi)
{
    const float* Ab = A + (size_t)blockIdx.z * strideA;
    float*       Cb = C + (size_t)blockIdx.z * strideC;
    int bm = blockIdx.y * 128, bn = blockIdx.x * 128;
    __shared__ float As[16][136];
    __shared__ float Ws[16][136];
    int tid  = threadIdx.x;
    int warp = tid >> 5, lane = tid & 31;
    int wm = (warp & 1) * 64;
    int wn = (warp >> 1) * 32;
    int grp = lane >> 2, tig = lane & 3;
    int lr = tid & 127, lc = (tid >> 7) * 8;

    float acc[4][4][4];
#pragma unroll
    for (int mt = 0; mt < 4; mt++)
#pragma unroll
        for (int nt = 0; nt < 4; nt++)
#pragma unroll
            for (int r = 0; r < 4; r++) acc[mt][nt][r] = 0.f;

    for (int k0 = 0; k0 < K; k0 += 16) {
        float4 a0v = make_float4(0.f,0.f,0.f,0.f);
        float4 a1v = make_float4(0.f,0.f,0.f,0.f);
        if (bm + lr < M) {
            a0v = *(const float4*)&Ab[(size_t)(bm + lr) * K + k0 + lc];
            a1v = *(const float4*)&Ab[(size_t)(bm + lr) * K + k0 + lc + 4];
        }
        float4 w0v = *(const float4*)&W[(size_t)(bn + lr) * K + k0 + lc];
        float4 w1v = *(const float4*)&W[(size_t)(bn + lr) * K + k0 + lc + 4];
        As[lc+0][lr]=a0v.x; As[lc+1][lr]=a0v.y; As[lc+2][lr]=a0v.z; As[lc+3][lr]=a0v.w;
        As[lc+4][lr]=a1v.x; As[lc+5][lr]=a1v.y; As[lc+6][lr]=a1v.z; As[lc+7][lr]=a1v.w;
        Ws[lc+0][lr]=w0v.x; Ws[lc+1][lr]=w0v.y; Ws[lc+2][lr]=w0v.z; Ws[lc+3][lr]=w0v.w;
        Ws[lc+4][lr]=w1v.x; Ws[lc+5][lr]=w1v.y; Ws[lc+6][lr]=w1v.z; Ws[lc+7][lr]=w1v.w;
        __syncthreads();

#pragma unroll
        for (int ks = 0; ks < 16; ks += 8) {
            uint32_t af[4][4];
            uint32_t bf[4][2];
#pragma unroll
            for (int mt = 0; mt < 4; mt++) {
                int mb = wm + mt * 16;
                af[mt][0] = f2tf32(As[ks + tig    ][mb + grp    ]);
                af[mt][1] = f2tf32(As[ks + tig    ][mb + grp + 8]);
                af[mt][2] = f2tf32(As[ks + tig + 4][mb + grp    ]);
                af[mt][3] = f2tf32(As[ks + tig + 4][mb + grp + 8]);
            }
#pragma unroll
            for (int nt = 0; nt < 4; nt++) {
                int nb = wn + nt * 8;
                bf[nt][0] = f2tf32(Ws[ks + tig    ][nb + grp]);
                bf[nt][1] = f2tf32(Ws[ks + tig + 4][nb + grp]);
            }
#pragma unroll
            for (int mt = 0; mt < 4; mt++)
#pragma unroll
                for (int nt = 0; nt < 4; nt++)
                    mma_tf32(acc[mt][nt], af[mt], bf[nt]);
        }
        __syncthreads();
    }

#pragma unroll
    for (int mt = 0; mt < 4; mt++) {
#pragma unroll
        for (int nt = 0; nt < 4; nt++) {
            int row0 = bm + wm + mt * 16 + grp;
            int col0 = bn + wn + nt * 8 + tig * 2;
            float b0 = bias[col0], b1 = bias[col0 + 1];
            if (row0 < M) {
                float v0 = acc[mt][nt][0] + b0;
                float v1 = acc[mt][nt][1] + b1;
                size_t i0 = (size_t)row0 * N + col0;
                if (epi == 1) { v0 = fmaxf(v0, 0.f); v1 = fmaxf(v1, 0.f); }
                if (epi == 2) { Cb[i0] += v0; Cb[i0 + 1] += v1; }
                else          { Cb[i0]  = v0; Cb[i0 + 1]  = v1; }
            }
            if (row0 + 8 < M) {
                float v2 = acc[mt][nt][2] + b0;
                float v3 = acc[mt][nt][3] + b1;
                size_t i2 = (size_t)(row0 + 8) * N + col0;
                if (epi == 1) { v2 = fmaxf(v2, 0.f); v3 = fmaxf(v3, 0.f); }
                if (epi == 2) { Cb[i2] += v2; Cb[i2 + 1] += v3; }
                else          { Cb[i2]  = v2; Cb[i2 + 1]  = v3; }
            }
        }
    }
}

// cls token into row 0, wrap rows 16001..16129 from rows 1..129
__global__ void k_fixup(const float* __restrict__ cls)
{
    int b = blockIdx.y, r = blockIdx.x, c = threadIdx.x; // 512 thr
    if (r == 0) g_h[(size_t)b * NTOK * D + c] = cls[c];
    else {
        int j = r - 1;
        g_h[((size_t)b*NTOK + 16001 + j)*D + c] = g_h[((size_t)b*NTOK + 1 + j)*D + c];
    }
}

__global__ void k_lnpad(const float* __restrict__ hin,
                        const float* __restrict__ w, const float* __restrict__ b)
{
    int row = blockIdx.x, bb = blockIdx.y, t = threadIdx.x; // 256 thr
    float* out = g_xpad + ((size_t)bb * NPAD + row) * D;
    if (row < PAD0) { out[t] = 0.f; out[t+256] = 0.f; return; }
    const float* in = hin + ((size_t)bb * NTOK + row - PAD0) * D;
    float x0 = in[t], x1 = in[t+256];
    __shared__ float red[256];
    red[t] = x0 + x1; __syncthreads();
    for (int s = 128; s > 0; s >>= 1) { if (t < s) red[t] += red[t+s]; __syncthreads(); }
    float mu = red[0] * (1.f/512.f); __syncthreads();
    float d0 = x0 - mu, d1 = x1 - mu;
    red[t] = d0*d0 + d1*d1; __syncthreads();
    for (int s = 128; s > 0; s >>= 1) { if (t < s) red[t] += red[t+s]; __syncthreads(); }
    float rs = rsqrtf(red[0] * (1.f/512.f) + LNEPS);
    out[t]     = d0 * rs * w[t]     + b[t];
    out[t+256] = d1 * rs * w[t+256] + b[t+256];
}

__global__ void k_landmarks()
{
    int bh = blockIdx.y, j = blockIdx.x, dd = threadIdx.x; // 64 thr
    int b = bh >> 3, hh = bh & 7;
    const float* base = g_qkv + ((size_t)b*NPAD + (size_t)j*64)*QKV3 + hh*HD + dd;
    float sq = 0.f, sk = 0.f;
    for (int t = 0; t < 64; t++) {
        sq += base[(size_t)t*QKV3];
        sk += base[(size_t)t*QKV3 + D];
    }
    g_ql[((size_t)bh*M_LM + j)*HD + dd] = sq * (1.f/64.f) * 0.125f;
    g_kl[((size_t)bh*M_LM + j)*HD + dd] = sk * (1.f/64.f);
}

__global__ void k_attn2()
{
    int bh = blockIdx.y, j = blockIdx.x, t = threadIdx.x; // 256 thr
    __shared__ float qrow[64];
    __shared__ float red[256];
    if (t < 64) qrow[t] = g_ql[((size_t)bh*M_LM + j)*HD + t];
    __syncthreads();
    const float* kr = g_kl + ((size_t)bh*M_LM + t)*HD;
    float s = 0.f;
#pragma unroll
    for (int dd = 0; dd < 64; dd++) s = fmaf(qrow[dd], kr[dd], s);
    red[t] = s; __syncthreads();
    for (int st = 128; st > 0; st >>= 1) { if (t < st) red[t] = fmaxf(red[t], red[t+st]); __syncthreads(); }
    float mx = red[0]; __syncthreads();
    float e = expf(s - mx);
    red[t] = e; __syncthreads();
    for (int st = 128; st > 0; st >>= 1) { if (t < st) red[t] += red[t+st]; __syncthreads(); }
    g_a2[((size_t)bh*M_LM + j)*M_LM + t] = e / red[0];
}

__global__ void k_scale_init() { g_rmax = 0; g_cmax = 0; }

__global__ void k_scale_reduce()
{
    int bh = blockIdx.x, t = threadIdx.x; // 256 thr
    const float* a = g_a2 + (size_t)bh * M_LM * M_LM;
    float cs = 0.f, rs = 0.f;
    for (int j = 0; j < 256; j++) cs += a[(size_t)j*256 + t];
    for (int i = 0; i < 256; i++) rs += a[(size_t)t*256 + i];
    __shared__ float red[256];
    red[t] = cs; __syncthreads();
    for (int s = 128; s > 0; s >>= 1) { if (t < s) red[t] = fmaxf(red[t], red[t+s]); __syncthreads(); }
    if (t == 0) atomicMax(&g_cmax, __float_as_int(red[0]));
    __syncthreads();
    red[t] = rs; __syncthreads();
    for (int s = 128; s > 0; s >>= 1) { if (t < s) red[t] = fmaxf(red[t], red[t+s]); __syncthreads(); }
    if (t == 0) atomicMax(&g_rmax, __float_as_int(red[0]));
}

__global__ void k_zinit()
{
    int bh = blockIdx.y, i = blockIdx.x, j = threadIdx.x; // 256 thr
    float scale = __int_as_float(g_rmax) * __int_as_float(g_cmax);
    g_z0[((size_t)bh*M_LM + i)*M_LM + j] = g_a2[((size_t)bh*M_LM + j)*M_LM + i] / scale;
}

// Dst = post * X @ (diag*I + sY*Y), 256x256 per bh  (tf32 tensor core)
// BM=BN=64, BK=32, 128 threads (4 warps), warp tile 32x32.
__global__ void __launch_bounds__(128) k_bmm256(
    const float* __restrict__ X, const float* __restrict__ Y,
    float* __restrict__ Dst, float diag, float sY, float post)
{
    size_t off = (size_t)blockIdx.z * M_LM * M_LM;
    X += off; Y += off; Dst += off;
    int bm = blockIdx.y * 64, bn = blockIdx.x * 64;
    __shared__ float Xs[32][72];   // [k][m]
    __shared__ float Ys[32][72];   // [k][n]
    int tid = threadIdx.x;
    int warp = tid >> 5, lane = tid & 31;
    int wm = (warp & 1) * 32, wn = (warp >> 1) * 32;
    int grp = lane >> 2, tig = lane & 3;
    float acc[2][4][4] = {};

    for (int k0 = 0; k0 < 256; k0 += 32) {
        for (int idx = tid; idx < 2048; idx += 128) {
            int m = idx >> 5, kk = idx & 31;
            Xs[kk][m] = X[(size_t)(bm+m)*256 + k0 + kk];
        }
        for (int idx = tid; idx < 2048; idx += 128) {
            int kk = idx >> 6, n = idx & 63;
            int gk = k0 + kk, gn = bn + n;
            float v = sY * Y[(size_t)gk*256 + gn];
            if (gk == gn) v += diag;
            Ys[kk][n] = v;
        }
        __syncthreads();
#pragma unroll
        for (int ks = 0; ks < 32; ks += 8) {
            uint32_t af[2][4], bf[4][2];
#pragma unroll
            for (int mt = 0; mt < 2; mt++) {
                int mb = wm + mt * 16;
                af[mt][0] = f2tf32(Xs[ks + tig    ][mb + grp    ]);
                af[mt][1] = f2tf32(Xs[ks + tig    ][mb + grp + 8]);
                af[mt][2] = f2tf32(Xs[ks + tig + 4][mb + grp    ]);
                af[mt][3] = f2tf32(Xs[ks + tig + 4][mb + grp + 8]);
            }
#pragma unroll
            for (int nt = 0; nt < 4; nt++) {
                int nb = wn + nt * 8;
                bf[nt][0] = f2tf32(Ys[ks + tig    ][nb + grp]);
                bf[nt][1] = f2tf32(Ys[ks + tig + 4][nb + grp]);
            }
#pragma unroll
            for (int mt = 0; mt < 2; mt++)
#pragma unroll
                for (int nt = 0; nt < 4; nt++)
                    mma_tf32(acc[mt][nt], af[mt], bf[nt]);
        }
        __syncthreads();
    }
#pragma unroll
    for (int mt = 0; mt < 2; mt++)
#pragma unroll
        for (int nt = 0; nt < 4; nt++) {
            int row0 = bm + wm + mt * 16 + grp;
            int col0 = bn + wn + nt * 8 + tig * 2;
            Dst[(size_t)row0*256 + col0]         = post * acc[mt][nt][0];
            Dst[(size_t)row0*256 + col0 + 1]     = post * acc[mt][nt][1];
            Dst[(size_t)(row0+8)*256 + col0]     = post * acc[mt][nt][2];
            Dst[(size_t)(row0+8)*256 + col0 + 1] = post * acc[mt][nt][3];
        }
}

// C[m,n] = alpha * A[m,:64] . B[n,:64]  (tf32; per-(b,head) strided operands)
// BM=BN=64, K=64 fully staged; 256 threads (8 warps), warp tile 32x16.
__global__ void __launch_bounds__(256) k_gemm_k64(
    const float* __restrict__ A, long aSB, long aSH, int lda, float alpha,
    const float* __restrict__ Bp, long bSB, long bSH, int ldb,
    float* __restrict__ C, long cSB, long cSH, int ldc,
    int row0g, int rowEnd)
{
    int bh = blockIdx.z, b = bh >> 3, hh = bh & 7;
    const float* Ab = A  + (size_t)b*aSB + (size_t)hh*aSH;
    const float* Bbp= Bp + (size_t)b*bSB + (size_t)hh*bSH;
    float*       Cb = C  + (size_t)b*cSB + (size_t)hh*cSH;
    int bm = row0g + blockIdx.y * 64, bn = blockIdx.x * 64;
    __shared__ float As[64][72];   // [k][m]
    __shared__ float Bs[64][72];   // [k][n]
    int tid = threadIdx.x;
    int warp = tid >> 5, lane = tid & 31;
    int wm = (warp & 1) * 32, wn = (warp >> 1) * 16;
    int grp = lane >> 2, tig = lane & 3;

    for (int idx = tid; idx < 4096; idx += 256) {
        int m = idx >> 6, k = idx & 63;
        As[k][m] = (bm + m < rowEnd) ? Ab[(size_t)(bm+m)*lda + k] * alpha : 0.f;
    }
    for (int idx = tid; idx < 4096; idx += 256) {
        int n = idx >> 6, k = idx & 63;
        Bs[k][n] = Bbp[(size_t)(bn+n)*ldb + k];
    }
    __syncthreads();

    float acc[2][2][4] = {};
#pragma unroll
    for (int ks = 0; ks < 64; ks += 8) {
        uint32_t af[2][4], bf[2][2];
#pragma unroll
        for (int mt = 0; mt < 2; mt++) {
            int mb = wm + mt * 16;
            af[mt][0] = f2tf32(As[ks + tig    ][mb + grp    ]);
            af[mt][1] = f2tf32(As[ks + tig    ][mb + grp + 8]);
            af[mt][2] = f2tf32(As[ks + tig + 4][mb + grp    ]);
            af[mt][3] = f2tf32(As[ks + tig + 4][mb + grp + 8]);
        }
#pragma unroll
        for (int nt = 0; nt < 2; nt++) {
            int nb = wn + nt * 8;
            bf[nt][0] = f2tf32(Bs[ks + tig    ][nb + grp]);
            bf[nt][1] = f2tf32(Bs[ks + tig + 4][nb + grp]);
        }
#pragma unroll
        for (int mt = 0; mt < 2; mt++)
#pragma unroll
            for (int nt = 0; nt < 2; nt++)
                mma_tf32(acc[mt][nt], af[mt], bf[nt]);
    }

#pragma unroll
    for (int mt = 0; mt < 2; mt++)
#pragma unroll
        for (int nt = 0; nt < 2; nt++) {
            int row0 = bm + wm + mt * 16 + grp;
            int col0 = bn + wn + nt * 8 + tig * 2;
            if (row0 < rowEnd) {
                Cb[(size_t)row0*ldc + col0]     = acc[mt][nt][0];
                Cb[(size_t)row0*ldc + col0 + 1] = acc[mt][nt][1];
            }
            if (row0 + 8 < rowEnd) {
                Cb[(size_t)(row0+8)*ldc + col0]     = acc[mt][nt][2];
                Cb[(size_t)(row0+8)*ldc + col0 + 1] = acc[mt][nt][3];
            }
        }
}

__global__ void k_softmax(float* __restrict__ base, long strideBH, int row0, int N)
{
    int bh = blockIdx.y, row = row0 + blockIdx.x, t = threadIdx.x; // 256 thr
    float* p = base + (size_t)bh * strideBH + (size_t)row * N;
    __shared__ float red[256];
    float mx = -1e30f;
    for (int i = t; i < N; i += 256) mx = fmaxf(mx, p[i]);
    red[t] = mx; __syncthreads();
    for (int s = 128; s > 0; s >>= 1) { if (t < s) red[t] = fmaxf(red[t], red[t+s]); __syncthreads(); }
    mx = red[0]; __syncthreads();
    float sm = 0.f;
    for (int i = t; i < N; i += 256) { float e = expf(p[i] - mx); p[i] = e; sm += e; }
    red[t] = sm; __syncthreads();
    for (int s = 128; s > 0; s >>= 1) { if (t < s) red[t] += red[t+s]; __syncthreads(); }
    float inv = 1.f / red[0];
    for (int i = t; i < N; i += 256) p[i] *= inv;
}

// attn3(probs) @ v — tf32, split-K over 8 chunks of 2048.
// BM=32(j), BN=64(d), 256 threads (8 warps: 2 m x 4 n), warp tile 16x16.
__global__ void __launch_bounds__(256) k_av_part()
{
    int bh = blockIdx.z, b = bh >> 3, hh = bh & 7;
    int jt = blockIdx.y, ksb = blockIdx.x;
    int j0 = jt * 32;
    __shared__ float Ss[32][40];   // [k][j]
    __shared__ float Vs[32][72];   // [k][d]
    int tid = threadIdx.x;
    int warp = tid >> 5, lane = tid & 31;
    int wm = (warp & 1) * 16, wn = (warp >> 1) * 16;
    int grp = lane >> 2, tig = lane & 3;
    float acc[2][4] = {};
    const float* s3b = g_s3 + (size_t)bh * M_LM * NPAD;
    const float* vb  = g_qkv + (size_t)b * NPAD * QKV3 + 2*D + hh*HD;
    int i_beg = ksb * 2048;
    for (int i0 = i_beg; i0 < i_beg + 2048; i0 += 32) {
        for (int idx = tid; idx < 1024; idx += 256) {
            int j = idx >> 5, kk = idx & 31;
            Ss[kk][j] = s3b[(size_t)(j0+j)*NPAD + i0 + kk];
        }
        for (int idx = tid; idx < 2048; idx += 256) {
            int kk = idx >> 6, d2 = idx & 63;
            Vs[kk][d2] = vb[(size_t)(i0+kk)*QKV3 + d2];
        }
        __syncthreads();
#pragma unroll
        for (int ks = 0; ks < 32; ks += 8) {
            uint32_t af[4], bf[2][2];
            af[0] = f2tf32(Ss[ks + tig    ][wm + grp    ]);
            af[1] = f2tf32(Ss[ks + tig    ][wm + grp + 8]);
            af[2] = f2tf32(Ss[ks + tig + 4][wm + grp    ]);
            af[3] = f2tf32(Ss[ks + tig + 4][wm + grp + 8]);
#pragma unroll
            for (int nt = 0; nt < 2; nt++) {
                int nb = wn + nt * 8;
                bf[nt][0] = f2tf32(Vs[ks + tig    ][nb + grp]);
                bf[nt][1] = f2tf32(Vs[ks + tig + 4][nb + grp]);
            }
#pragma unroll
            for (int nt = 0; nt < 2; nt++)
                mma_tf32(acc[nt], af, bf[nt]);
        }
        __syncthreads();
    }
    size_t basep = (((size_t)bh*8 + ksb)*M_LM + j0) * HD;
#pragma unroll
    for (int nt = 0; nt < 2; nt++) {
        int row0 = wm + grp;
        int col0 = wn + nt * 8 + tig * 2;
        g_avp[basep + (size_t)row0*HD + col0]         = acc[nt][0];
        g_avp[basep + (size_t)row0*HD + col0 + 1]     = acc[nt][1];
        g_avp[basep + (size_t)(row0+8)*HD + col0]     = acc[nt][2];
        g_avp[basep + (size_t)(row0+8)*HD + col0 + 1] = acc[nt][3];
    }
}

__global__ void k_av_reduce()
{
    int idx = blockIdx.x * 256 + threadIdx.x;
    if (idx >= BH * M_LM * HD) return;
    int bh = idx / (M_LM * HD);
    int rem = idx % (M_LM * HD);
    float s = 0.f;
    for (int ks = 0; ks < 8; ks++)
        s += g_avp[((size_t)bh*8 + ks)*M_LM*HD + rem];
    g_av[idx] = s;
}

__global__ void k_mid(const float* __restrict__ z)
{
    int bh = blockIdx.y, j = blockIdx.x, dd = threadIdx.x; // 64 thr
    const float* zr = z + ((size_t)bh*M_LM + j)*M_LM;
    const float* av = g_av + (size_t)bh*M_LM*HD;
    float s = 0.f;
    for (int t = 0; t < 256; t++) s = fmaf(zr[t], av[(size_t)t*HD + dd], s);
    g_mid[((size_t)bh*M_LM + j)*HD + dd] = s;
}

__global__ void __launch_bounds__(256) k_a1mid(int row0, int rowEnd)
{
    int bh = blockIdx.y, b = bh >> 3, hh = bh & 7;
    int bm = row0 + blockIdx.x * 64;
    __shared__ float A1s[64][33];
    __shared__ float Ms[32][66];
    const float* a1  = g_a1  + (size_t)bh * NPAD * M_LM;
    const float* mid = g_mid + (size_t)bh * M_LM * HD;
    int tid = threadIdx.x, ty = tid >> 4, tx = tid & 15;
    float acc[4][4] = {};
    for (int k0 = 0; k0 < 256; k0 += 32) {
        for (int idx = tid; idx < 2048; idx += 256) {
            int m = idx >> 5, kk = idx & 31;
            A1s[m][kk] = (bm + m < rowEnd) ? a1[(size_t)(bm+m)*M_LM + k0 + kk] : 0.f;
        }
        for (int idx = tid; idx < 2048; idx += 256) {
            int kk = idx >> 6, d2 = idx & 63;
            Ms[kk][d2] = mid[(size_t)(k0+kk)*HD + d2];
        }
        __syncthreads();
#pragma unroll
        for (int kk = 0; kk < 32; kk++) {
            float a[4], bb[4];
#pragma unroll
            for (int i = 0; i < 4; i++) a[i] = A1s[ty*4+i][kk];
#pragma unroll
            for (int j = 0; j < 4; j++) bb[j] = Ms[kk][tx*4+j];
#pragma unroll
            for (int i = 0; i < 4; i++)
#pragma unroll
                for (int j = 0; j < 4; j++)
                    acc[i][j] = fmaf(a[i], bb[j], acc[i][j]);
        }
        __syncthreads();
    }
#pragma unroll
    for (int i = 0; i < 4; i++) {
        int row = bm + ty*4 + i;
        if (row >= rowEnd) continue;
#pragma unroll
        for (int j = 0; j < 4; j++)
            g_attnout[((size_t)b*NPAD + row)*D + hh*HD + tx*4+j] = acc[i][j];
    }
}

__global__ void k_dwconv(const float* __restrict__ w, int row0, int nrows)
{
    int idx = blockIdx.x * 256 + threadIdx.x;
    int b = blockIdx.y;
    if (idx >= nrows * D) return;
    int i = row0 + idx / D;
    int col = idx % D;
    int hd = col >> 6;
    float acc = g_attnout[((size_t)b*NPAD + i)*D + col];
#pragma unroll
    for (int t = 0; t < 33; t++) {
        int ii = i + t - 16;
        if (ii >= 0 && ii < NPAD)
            acc = fmaf(w[hd*33 + t], g_qkv[((size_t)b*NPAD + ii)*QKV3 + 2*D + col], acc);
    }
    g_attnout[((size_t)b*NPAD + i)*D + col] = acc;
}

// layer-2 cls-only out-proj: clsrow = h2[b,0,:] + attnout[b,254,:] @ W^T + bias
__global__ void k_outproj_cls(const float* __restrict__ W, const float* __restrict__ bias)
{
    int b = blockIdx.x, col = threadIdx.x; // 512 thr
    const float* arow = g_attnout + ((size_t)b*NPAD + PAD0)*D;
    const float* wrow = W + (size_t)col * D;
    float acc = bias[col];
    for (int k = 0; k < 512; k++) acc = fmaf(arow[k], wrow[k], acc);
    g_clsrow[b*D + col] = g_h2[(size_t)b*NTOK*D + col] + acc;
}

__global__ void k_ppeg(const float* __restrict__ hin, float* __restrict__ hout,
                       const float* __restrict__ w7, const float* __restrict__ b7,
                       const float* __restrict__ w5, const float* __restrict__ b5,
                       const float* __restrict__ w3, const float* __restrict__ b3)
{
    int pos = blockIdx.x, b = blockIdx.y, ch = threadIdx.x; // 512 thr
    if (pos == 0)
        hout[(size_t)b*NTOK*D + ch] = hin[(size_t)b*NTOK*D + ch];
    int r = pos / HW, c = pos % HW;
    const float* fb = hin + ((size_t)b*NTOK + 1)*D + ch;
    float acc = fb[(size_t)pos*D] + b7[ch] + b5[ch] + b3[ch];
    for (int ky = 0; ky < 7; ky++) {
        int rr = r + ky - 3;
        if (rr < 0 || rr >= HW) continue;
        for (int kx = 0; kx < 7; kx++) {
            int cc = c + kx - 3;
            if (cc < 0 || cc >= HW) continue;
            float v = fb[(size_t)(rr*HW + cc)*D];
            float ws = w7[(size_t)ch*49 + ky*7 + kx];
            if (ky >= 1 && ky <= 5 && kx >= 1 && kx <= 5)
                ws += w5[(size_t)ch*25 + (ky-1)*5 + (kx-1)];
            if (ky >= 2 && ky <= 4 && kx >= 2 && kx <= 4)
                ws += w3[(size_t)ch*9 + (ky-2)*3 + (kx-2)];
            acc = fmaf(ws, v, acc);
        }
    }
    hout[((size_t)b*NTOK + 1 + pos)*D + ch] = acc;
}

__global__ void k_final(const float* __restrict__ nw, const float* __restrict__ nb,
                        const float* __restrict__ fw, const float* __restrict__ fbias,
                        float* __restrict__ out)
{
    int b = blockIdx.x, t = threadIdx.x; // 256 thr
    const float* cls = g_clsrow + (size_t)b * D;
    float x0 = cls[t], x1 = cls[t+256];
    __shared__ float red[256];
    red[t] = x0 + x1; __syncthreads();
    for (int s = 128; s > 0; s >>= 1) { if (t < s) red[t] += red[t+s]; __syncthreads(); }
    float mu = red[0] * (1.f/512.f); __syncthreads();
    float d0 = x0 - mu, d1 = x1 - mu;
    red[t] = d0*d0 + d1*d1; __syncthreads();
    for (int s = 128; s > 0; s >>= 1) { if (t < s) red[t] += red[t+s]; __syncthreads(); }
    float rs = rsqrtf(red[0] * (1.f/512.f) + LNEPS); __syncthreads();
    float n0 = d0 * rs * nw[t]     + nb[t];
    float n1 = d1 * rs * nw[t+256] + nb[t+256];
    red[t] = n0 * fw[t] + n1 * fw[t+256]; __syncthreads();
    for (int s = 128; s > 0; s >>= 1) { if (t < s) red[t] += red[t+s]; __syncthreads(); }
    float o0 = red[0] + fbias[0]; __syncthreads();
    red[t] = n0 * fw[512+t] + n1 * fw[512+t+256]; __syncthreads();
    for (int s = 128; s > 0; s >>= 1) { if (t < s) red[t] += red[t+s]; __syncthreads(); }
    float o1 = red[0] + fbias[1];
    if (t == 0) { out[b*2+0] = o0; out[b*2+1] = o1; }
}

// ---------------------------------------------------------------------------
extern "C" void kernel_launch(void* const* d_in, const int* in_sizes, int n_in,
                              void* d_out, int out_size)
{
    (void)in_sizes; (void)n_in; (void)out_size;
    const float* x       = (const float*)d_in[0];
    const float* fc1_w   = (const float*)d_in[1];
    const float* fc1_b   = (const float*)d_in[2];
    const float* cls_tok = (const float*)d_in[3];
    const float* ln_w    = (const float*)d_in[4];
    const float* ln_b    = (const float*)d_in[5];
    const float* qkv_w   = (const float*)d_in[6];
    const float* qkv_b   = (const float*)d_in[7];
    const float* aout_w  = (const float*)d_in[8];
    const float* aout_b  = (const float*)d_in[9];
    const float* res_w   = (const float*)d_in[10];
    const float* w7 = (const float*)d_in[11];
    const float* b7 = (const float*)d_in[12];
    const float* w5 = (const float*)d_in[13];
    const float* b5 = (const float*)d_in[14];
    const float* w3 = (const float*)d_in[15];
    const float* b3 = (const float*)d_in[16];
    const float* norm_w = (const float*)d_in[17];
    const float* norm_b = (const float*)d_in[18];
    const float* fc2_w  = (const float*)d_in[19];
    const float* fc2_b  = (const float*)d_in[20];
    float* out = (float*)d_out;

    float *ph, *ph2, *pxpad, *pqkv, *pz0, *pz1, *paz, *pt2, *pt4;
    cudaGetSymbolAddress((void**)&ph, g_h);
    cudaGetSymbolAddress((void**)&ph2, g_h2);
    cudaGetSymbolAddress((void**)&pxpad, g_xpad);
    cudaGetSymbolAddress((void**)&pqkv, g_qkv);
    cudaGetSymbolAddress((void**)&pz0, g_z0);
    cudaGetSymbolAddress((void**)&pz1, g_z1);
    cudaGetSymbolAddress((void**)&paz, g_az);
    cudaGetSymbolAddress((void**)&pt2, g_t2);
    cudaGetSymbolAddress((void**)&pt4, g_t4);
    float *pa2, *pql, *ps3, *pa1, *pao;
    cudaGetSymbolAddress((void**)&pa2, g_a2);
    cudaGetSymbolAddress((void**)&pql, g_ql);
    cudaGetSymbolAddress((void**)&ps3, g_s3);
    cudaGetSymbolAddress((void**)&pa1, g_a1);
    cudaGetSymbolAddress((void**)&pao, g_attnout);
    float* pkl; cudaGetSymbolAddress((void**)&pkl, g_kl);

    // fc1: h[:,1:16001] = relu(x @ fc1_w^T)
    k_sgemm<<<dim3(4, 125, Bb), 256>>>(x, fc1_w, fc1_b, ph + D,
                                       16000, D, DIN,
                                       (long)16000 * DIN, (long)NTOK * D, 1);
    k_fixup<<<dim3(130, Bb), 512>>>(cls_tok);

    for (int l = 0; l < 2; l++) {
        const float* hin = (l == 0) ? ph : ph2;
        bool clsOnly = (l == 1);

        k_lnpad<<<dim3(NPAD, Bb), 256>>>(hin, ln_w + l*D, ln_b + l*D);
        k_sgemm<<<dim3(12, 128, Bb), 256>>>(pxpad, qkv_w + (size_t)l*QKV3*D,
                                            qkv_b + l*QKV3, pqkv,
                                            NPAD, QKV3, D,
                                            (long)NPAD * D, (long)NPAD * QKV3, 0);
        k_landmarks<<<dim3(M_LM, BH), 64>>>();
        k_attn2<<<dim3(M_LM, BH), 256>>>();
        k_scale_init<<<1, 1>>>();
        k_scale_reduce<<<BH, 256>>>();
        k_zinit<<<dim3(M_LM, BH), 256>>>();

        float* zc = pz0; float* zn = pz1;
        for (int it = 0; it < 6; it++) {
            k_bmm256<<<dim3(4,4,BH), 128>>>(pa2, zc, paz, 0.f, 1.f, 1.f);
            k_bmm256<<<dim3(4,4,BH), 128>>>(paz, paz, pt2, 7.f, -1.f, 1.f);
            k_bmm256<<<dim3(4,4,BH), 128>>>(paz, pt2, pt4, 15.f, -1.f, 1.f);
            k_bmm256<<<dim3(4,4,BH), 128>>>(zc, pt4, zn, 13.f, -1.f, 0.25f);
            float* tmp = zc; zc = zn; zn = tmp;
        }
        // zc holds the final pinv

        // attn3 logits + softmax
        k_gemm_k64<<<dim3(256, 4, BH), 256>>>(
            pql, (long)8*M_LM*HD, (long)M_LM*HD, HD, 1.f,
            pqkv + D, (long)NPAD*QKV3, (long)HD, QKV3,
            ps3, (long)8*M_LM*NPAD, (long)M_LM*NPAD, NPAD, 0, M_LM);
        k_softmax<<<dim3(M_LM, BH), 256>>>(ps3, (long)M_LM*NPAD, 0, NPAD);
        k_av_part<<<dim3(8, 8, BH), 256>>>();
        k_av_reduce<<<(BH*M_LM*HD + 255)/256, 256>>>();
        k_mid<<<dim3(M_LM, BH), 64>>>(zc);

        // attn1 logits + softmax + @mid (pruned on layer 2)
        int row0 = PAD0;
        int nrows = clsOnly ? 1 : NTOK;
        int rowEnd = clsOnly ? (PAD0 + 1) : NPAD;
        int ntiles = (nrows + 63) / 64;
        k_gemm_k64<<<dim3(4, ntiles, BH), 256>>>(
            pqkv, (long)NPAD*QKV3, (long)HD, QKV3, 0.125f,
            pkl, (long)8*M_LM*HD, (long)M_LM*HD, HD,
            pa1, (long)8*NPAD*M_LM, (long)NPAD*M_LM, M_LM, row0, rowEnd);
        k_softmax<<<dim3(nrows, BH), 256>>>(pa1, (long)NPAD*M_LM, row0, M_LM);
        k_a1mid<<<dim3(ntiles, BH), 256>>>(row0, rowEnd);
        k_dwconv<<<dim3((nrows*D + 255)/256, Bb), 256>>>(res_w + l*8*33, row0, nrows);

        if (!clsOnly) {
            // h += attnout[:, 254:, :] @ aout_w^T + aout_b
            k_sgemm<<<dim3(4, (NTOK + 127)/128, Bb), 256>>>(
                pao + (size_t)PAD0 * D, aout_w + (size_t)l*D*D, aout_b + l*D, ph,
                NTOK, D, D, (long)NPAD * D, (long)NTOK * D, 2);
            k_ppeg<<<dim3(NFEAT, Bb), 512>>>(ph, ph2, w7, b7, w5, b5, w3, b3);
        } else {
            k_outproj_cls<<<Bb, 512>>>(aout_w + (size_t)l*D*D, aout_b + l*D);
        }
    }

    k_final<<<Bb, 256>>>(norm_w, norm_b, fc2_w, fc2_b, out);
}